// round 9
// baseline (speedup 1.0000x reference)
#include <cuda_runtime.h>
#include <cuda_fp16.h>
#include <cstdint>

#define DEVI __device__ __forceinline__

constexpr int B_  = 2;
constexpr int L_  = 4096;
constexpr int D_  = 512;
constexpr int H_  = 8;
constexpr int HD_ = 64;
constexpr int M_  = B_ * L_;          // 8192
constexpr size_t MD = (size_t)M_*D_;  // 4194304
constexpr size_t DD = (size_t)D_*D_;  // 262144

// scratch: __device__ globals (allocation-free rule)
__device__ __half g_x16[3*MD];          // fp16 copies of query,key,value
__device__ __half g_w16[4*DD];          // fp16 copies of Wq,Wk,Wv,Wo
__device__ __half g_qh[B_*H_*L_*HD_];   // [b,h,l,d] (pre-scaled by 0.125*log2e)
__device__ __half g_kh[B_*H_*L_*HD_];   // [b,h,l,d]
__device__ __half g_vt[B_*H_*HD_*L_];   // [b,h,d,l]  (transposed)
__device__ __half g_ctx16[MD];          // attention output, fp16

DEVI uint32_t h2u(__half2 h){ union{ __half2 h; uint32_t u; } c; c.h = h; return c.u; }

DEVI void mma_f16(float* c, const uint32_t* a, const uint32_t* b){
  asm volatile("mma.sync.aligned.m16n8k16.row.col.f32.f16.f16.f32 "
    "{%0,%1,%2,%3},{%4,%5,%6,%7},{%8,%9},{%0,%1,%2,%3};\n"
    : "+f"(c[0]),"+f"(c[1]),"+f"(c[2]),"+f"(c[3])
    : "r"(a[0]),"r"(a[1]),"r"(a[2]),"r"(a[3]),"r"(b[0]),"r"(b[1]));
}

DEVI void ldsm4(uint32_t& r0, uint32_t& r1, uint32_t& r2, uint32_t& r3, uint32_t addr){
  asm volatile("ldmatrix.sync.aligned.m8n8.x4.shared.b16 {%0,%1,%2,%3}, [%4];"
    : "=r"(r0),"=r"(r1),"=r"(r2),"=r"(r3) : "r"(addr));
}
DEVI void ldsm4t(uint32_t& r0, uint32_t& r1, uint32_t& r2, uint32_t& r3, uint32_t addr){
  asm volatile("ldmatrix.sync.aligned.m8n8.x4.trans.shared.b16 {%0,%1,%2,%3}, [%4];"
    : "=r"(r0),"=r"(r1),"=r"(r2),"=r"(r3) : "r"(addr));
}

DEVI void cpa16(void* s, const void* g){
  uint32_t sa = (uint32_t)__cvta_generic_to_shared(s);
  asm volatile("cp.async.cg.shared.global [%0], [%1], 16;\n"::"r"(sa),"l"(g));
}
DEVI void cpa_commit(){ asm volatile("cp.async.commit_group;\n"); }
template<int N> DEVI void cpa_wait(){ asm volatile("cp.async.wait_group %0;\n"::"n"(N)); }

// ---------------------------------------------------------------------------
// conv16: round inputs + weights to fp16 once
// ---------------------------------------------------------------------------
__global__ void conv16(const float* __restrict__ q, const float* __restrict__ k,
                       const float* __restrict__ v,
                       const float* __restrict__ wq, const float* __restrict__ wk,
                       const float* __restrict__ wv, const float* __restrict__ wo)
{
  size_t i = ((size_t)blockIdx.x*blockDim.x + threadIdx.x)*4;
  if(i < MD){
    float4 a;
    a = *(const float4*)(q+i);
    *(__half2*)(g_x16 + i)        = __floats2half2_rn(a.x,a.y);
    *(__half2*)(g_x16 + i + 2)    = __floats2half2_rn(a.z,a.w);
    a = *(const float4*)(k+i);
    *(__half2*)(g_x16 + MD + i)   = __floats2half2_rn(a.x,a.y);
    *(__half2*)(g_x16 + MD + i+2) = __floats2half2_rn(a.z,a.w);
    a = *(const float4*)(v+i);
    *(__half2*)(g_x16 + 2*MD + i)   = __floats2half2_rn(a.x,a.y);
    *(__half2*)(g_x16 + 2*MD + i+2) = __floats2half2_rn(a.z,a.w);
  }
  if(i < DD){
    float4 a;
    a = *(const float4*)(wq+i);
    *(__half2*)(g_w16 + i)        = __floats2half2_rn(a.x,a.y);
    *(__half2*)(g_w16 + i + 2)    = __floats2half2_rn(a.z,a.w);
    a = *(const float4*)(wk+i);
    *(__half2*)(g_w16 + DD + i)   = __floats2half2_rn(a.x,a.y);
    *(__half2*)(g_w16 + DD + i+2) = __floats2half2_rn(a.z,a.w);
    a = *(const float4*)(wv+i);
    *(__half2*)(g_w16 + 2*DD + i)   = __floats2half2_rn(a.x,a.y);
    *(__half2*)(g_w16 + 2*DD + i+2) = __floats2half2_rn(a.z,a.w);
    a = *(const float4*)(wo+i);
    *(__half2*)(g_w16 + 3*DD + i)   = __floats2half2_rn(a.x,a.y);
    *(__half2*)(g_w16 + 3*DD + i+2) = __floats2half2_rn(a.z,a.w);
  }
}

// ---------------------------------------------------------------------------
// fp16 GEMM: C[M,512] = A[M,512] @ W[512,512] + bias   (fp32 accum)
// mode = mode_base + blockIdx.z:
//   1/2: fp16 scatter to g_qh/g_kh (mode 1 scaled by 0.125*log2e)
//   3:   fp16 transposed scatter to g_vt
//   4:   A = g_ctx16, plain f32 out + bias
// ---------------------------------------------------------------------------
constexpr int GBM = 128, GBN = 128, GBK = 64;
constexpr int GAW = 36;   // A row stride (words)
constexpr int GBW = 68;   // B row stride (words)
constexpr int GA_WORDS = GBM*GAW;   // 4608
constexpr int GB_WORDS = GBK*GBW;   // 4352
constexpr int GEMM16_SMEM = (2*GA_WORDS + 2*GB_WORDS)*4;   // 71680

__global__ void __launch_bounds__(256,2) gemm_f16(
  const float* __restrict__ bq, const float* __restrict__ bk,
  const float* __restrict__ bv, const float* __restrict__ bo,
  float* __restrict__ out, int mode_base)
{
  extern __shared__ uint32_t smw[];
  uint32_t* Aw = smw;                    // [2][128][36]
  uint32_t* Bw = smw + 2*GA_WORDS;       // [2][64][68]

  int mode = mode_base + blockIdx.z;     // 1..3 or 4
  const __half* A = (mode==4) ? g_ctx16 : g_x16 + (size_t)(mode-1)*MD;
  const __half* W = g_w16 + (size_t)(mode-1)*DD;
  const float* bias = (mode==1)?bq : (mode==2)?bk : (mode==3)?bv : bo;

  int tid = threadIdx.x;
  int m0 = blockIdx.y*GBM, n0 = blockIdx.x*GBN;
  int w = tid>>5, lane = tid&31, g = lane>>2, tg = lane&3;
  int wm = (w>>1)*32, wn = (w&1)*64;

  uint32_t sbase = (uint32_t)__cvta_generic_to_shared(smw);
  int t8  = lane & 7;
  int lb1 = (lane>>3) & 1;
  int lb2 = lane>>4;
  uint32_t a0 = sbase + (uint32_t)((wm      + lb1*8 + t8)*GAW + lb2*4)*4;
  uint32_t a1 = sbase + (uint32_t)((wm + 16 + lb1*8 + t8)*GAW + lb2*4)*4;
  uint32_t bb = sbase + (uint32_t)(2*GA_WORDS)*4
              + (uint32_t)((lb1*8 + t8)*GBW)*4 + (uint32_t)(wn + lb2*8)*2;
  constexpr uint32_t ABUF = GA_WORDS*4, BBUF = GB_WORDS*4;
  constexpr uint32_t BKSTEP = 16*GBW*4;

  float acc[2][8][4];
  #pragma unroll
  for(int i=0;i<2;i++)
    #pragma unroll
    for(int j=0;j<8;j++)
      #pragma unroll
      for(int k2=0;k2<4;k2++) acc[i][j][k2]=0.f;

  auto load_tiles = [&](int buf, int kt){
    const __half* ga = A + (size_t)m0*D_ + kt*GBK;
    #pragma unroll
    for(int j=0;j<4;j++){
      int idx = tid + j*256;
      int r = idx>>3, c = idx&7;
      cpa16((char*)(Aw + buf*GA_WORDS + r*GAW) + c*16, ga + (size_t)r*D_ + c*8);
    }
    const __half* gb = W + (size_t)(kt*GBK)*D_ + n0;
    #pragma unroll
    for(int j=0;j<4;j++){
      int idx = tid + j*256;
      int r = idx>>4, c = idx&15;
      cpa16((char*)(Bw + buf*GB_WORDS + r*GBW) + c*16, gb + (size_t)r*D_ + c*8);
    }
  };

  load_tiles(0,0); cpa_commit();

  #pragma unroll 1
  for(int kt=0; kt<D_/GBK; kt++){
    if(kt+1 < D_/GBK){ load_tiles((kt+1)&1, kt+1); cpa_commit(); cpa_wait<1>(); }
    else             { cpa_wait<0>(); }
    __syncthreads();
    int buf = kt&1;
    uint32_t ac0 = a0 + buf*ABUF, ac1 = a1 + buf*ABUF;
    uint32_t bc  = bb + buf*BBUF;
    #pragma unroll
    for(int kk=0; kk<4; kk++){
      uint32_t af0[4], af1[4];
      ldsm4(af0[0],af0[1],af0[2],af0[3], ac0 + kk*32);
      ldsm4(af1[0],af1[1],af1[2],af1[3], ac1 + kk*32);
      #pragma unroll
      for(int j=0;j<4;j++){
        uint32_t b0,b1,b2,b3;
        ldsm4t(b0,b1,b2,b3, bc + kk*BKSTEP + j*32);
        uint32_t bfa[2] = {b0,b1}, bfb[2] = {b2,b3};
        mma_f16(acc[0][2*j  ], af0, bfa);
        mma_f16(acc[0][2*j+1], af0, bfb);
        mma_f16(acc[1][2*j  ], af1, bfa);
        mma_f16(acc[1][2*j+1], af1, bfb);
      }
    }
    __syncthreads();
  }

  float oscale = (mode==1) ? 0.125f*1.44269504f : 1.0f;
  #pragma unroll
  for(int im=0;im<2;im++){
    int r0 = m0 + wm + im*16 + g;
    int r8 = r0 + 8;
    #pragma unroll
    for(int in=0;in<8;in++){
      int col = n0 + wn + in*8 + tg*2;
      float bx = bias[col], by = bias[col+1];
      float2 v0 = make_float2(acc[im][in][0]+bx, acc[im][in][1]+by);
      float2 v1 = make_float2(acc[im][in][2]+bx, acc[im][in][3]+by);
      if(mode==4){
        *(float2*)(out + (size_t)r0*D_ + col) = v0;
        *(float2*)(out + (size_t)r8*D_ + col) = v1;
      } else {
        int h = col>>6, d = col&63;
        int b0i = r0>>12, t0 = r0&4095;
        int b1i = r8>>12, t1 = r8&4095;
        if(mode==3){
          size_t i0 = ((size_t)(b0i*H_ + h)*HD_ + d)*L_ + t0;
          size_t i1 = ((size_t)(b1i*H_ + h)*HD_ + d)*L_ + t1;
          g_vt[i0]      = __float2half_rn(v0.x);
          g_vt[i0 + L_] = __float2half_rn(v0.y);
          g_vt[i1]      = __float2half_rn(v1.x);
          g_vt[i1 + L_] = __float2half_rn(v1.y);
        } else {
          __half* C = (mode==1) ? g_qh : g_kh;
          size_t i0 = ((size_t)(b0i*H_ + h)*L_ + t0)*HD_ + d;
          size_t i1 = ((size_t)(b1i*H_ + h)*L_ + t1)*HD_ + d;
          *(__half2*)(C + i0) = __floats2half2_rn(v0.x*oscale, v0.y*oscale);
          *(__half2*)(C + i1) = __floats2half2_rn(v1.x*oscale, v1.y*oscale);
        }
      }
    }
  }
}

// ---------------------------------------------------------------------------
// Flash attention: 4 warps x 32 q-rows per CTA (FM=128), 2 CTAs/SM so
// softmax/barrier stalls of one CTA overlap with MMAs of the other.
// Q frags in registers; K/V frags loaded once per warp, reused by both
// row-blocks. exp2-domain softmax (Q pre-scaled by 0.125*log2e).
// ---------------------------------------------------------------------------
constexpr int FM = 128, FN = 64, FNT = 128;   // FNT = threads per CTA
constexpr int RSW = 36;                 // row stride in 32-bit words
constexpr int Q_WORDS = FM*RSW;         // 4608
constexpr int K_WORDS = FN*RSW;         // 2304
constexpr int V_WORDS = FN*RSW;         // 2304
constexpr int FLASH_SMEM = (Q_WORDS + 2*K_WORDS + 2*V_WORDS)*4 + 2*FN*4;

__global__ void __launch_bounds__(FNT,2) flash_attn(const int* __restrict__ mask)
{
  extern __shared__ uint32_t smw[];
  uint32_t* Qw = smw;                    // [128][36]
  uint32_t* Kw = smw + Q_WORDS;          // [2][64][36]
  uint32_t* Vw = Kw + 2*K_WORDS;         // [2][64][36]  (V^T: row=d, col=key)
  int*      Ms = (int*)(Vw + 2*V_WORDS);

  int tid = threadIdx.x, w = tid>>5, lane = tid&31, g = lane>>2, tg = lane&3;
  int bh = blockIdx.y;
  int b  = bh >> 3;
  int q0 = blockIdx.x * FM;
  int rb = w*32;

  const __half* Qg = g_qh + (size_t)bh*L_*HD_ + (size_t)q0*HD_;
  const __half* Kg = g_kh + (size_t)bh*L_*HD_;
  const __half* Vg = g_vt + (size_t)bh*HD_*L_;
  const int*    mg = mask + b*L_;

  uint32_t smem_base = (uint32_t)__cvta_generic_to_shared(smw);
  int t8  = lane & 7;
  int lb1 = (lane>>3) & 1;
  int lb2 = lane>>4;
  uint32_t qaddr0 = smem_base + (uint32_t)((rb      + lb1*8 + t8)*RSW + lb2*4)*4;
  uint32_t qaddr1 = smem_base + (uint32_t)((rb + 16 + lb1*8 + t8)*RSW + lb2*4)*4;
  uint32_t kvoff = (uint32_t)(((lb2*8 + t8)*RSW) + lb1*4)*4;
  uint32_t kbase = smem_base + (uint32_t)Q_WORDS*4 + kvoff;
  uint32_t vbase = smem_base + (uint32_t)(Q_WORDS + 2*K_WORDS)*4 + kvoff;
  constexpr uint32_t PSTRIDE = 16*RSW*4;
  constexpr uint32_t KBUF = K_WORDS*4, VBUF = V_WORDS*4;

  // Q tile: 128 rows x 8 chunks = 1024 chunks / 128 threads
  #pragma unroll
  for(int j=0;j<8;j++){
    int idx = tid + j*FNT;
    int r = idx>>3, c = idx&7;
    cpa16((char*)(Qw + r*RSW) + c*16, Qg + (size_t)r*HD_ + c*8);
  }
  cpa_commit();

  auto loadKV = [&](int buf, int it){
    const __half* kg = Kg + (size_t)it*FN*HD_;
    const __half* vg = Vg + it*FN;
    #pragma unroll
    for(int j=0;j<4;j++){                 // K: 512 chunks / 128 threads
      int idx = tid + j*FNT;
      int r = idx>>3, c = idx&7;
      cpa16((char*)(Kw + buf*K_WORDS + r*RSW) + c*16, kg + (size_t)r*HD_ + c*8);
    }
    #pragma unroll
    for(int j=0;j<4;j++){                 // V^T
      int idx = tid + j*FNT;
      int r = idx>>3, c = idx&7;
      cpa16((char*)(Vw + buf*V_WORDS + r*RSW) + c*16, vg + (size_t)r*L_ + c*8);
    }
    if(tid < 16) cpa16(&Ms[buf*FN + tid*4], mg + it*FN + tid*4);
  };

  cpa_wait<0>();
  __syncthreads();
  uint32_t qf[2][4][4];
  #pragma unroll
  for(int kk=0;kk<4;kk++){
    ldsm4(qf[0][kk][0],qf[0][kk][1],qf[0][kk][2],qf[0][kk][3], qaddr0 + kk*32);
    ldsm4(qf[1][kk][0],qf[1][kk][1],qf[1][kk][2],qf[1][kk][3], qaddr1 + kk*32);
  }

  loadKV(0,0); cpa_commit();

  float o[2][8][4];
  #pragma unroll
  for(int m=0;m<2;m++)
    #pragma unroll
    for(int i=0;i<8;i++)
      #pragma unroll
      for(int j=0;j<4;j++) o[m][i][j]=0.f;
  float mo[4] = {-1e30f,-1e30f,-1e30f,-1e30f};
  float lo[4] = {0.f,0.f,0.f,0.f};

  #pragma unroll 1
  for(int it=0; it<L_/FN; it++){
    int buf = it&1;
    if(it+1 < L_/FN){ loadKV(buf^1, it+1); cpa_commit(); cpa_wait<1>(); }
    else            { cpa_wait<0>(); }
    __syncthreads();

    uint32_t kab = kbase + buf*KBUF;
    uint32_t vab = vbase + buf*VBUF;
    const int* ms = Ms + buf*FN;

    float s[2][8][4];
    #pragma unroll
    for(int m=0;m<2;m++)
      #pragma unroll
      for(int i=0;i<8;i++)
        #pragma unroll
        for(int j=0;j<4;j++) s[m][i][j]=0.f;

    #pragma unroll
    for(int kk=0; kk<4; kk++){
      #pragma unroll
      for(int p=0;p<4;p++){
        uint32_t b0,b1,b2,b3;
        ldsm4(b0,b1,b2,b3, kab + p*PSTRIDE + kk*32);
        uint32_t bfa[2] = {b0,b1}, bfb[2] = {b2,b3};
        mma_f16(s[0][2*p  ], qf[0][kk], bfa);
        mma_f16(s[0][2*p+1], qf[0][kk], bfb);
        mma_f16(s[1][2*p  ], qf[1][kk], bfa);
        mma_f16(s[1][2*p+1], qf[1][kk], bfb);
      }
    }

    #pragma unroll
    for(int m=0;m<2;m++){
      #pragma unroll
      for(int in=0;in<8;in++){
        int c0 = in*8 + tg*2;
        bool ok0 = ms[c0]!=0, ok1 = ms[c0+1]!=0;
        s[m][in][0] = ok0 ? s[m][in][0] : -1e30f;
        s[m][in][1] = ok1 ? s[m][in][1] : -1e30f;
        s[m][in][2] = ok0 ? s[m][in][2] : -1e30f;
        s[m][in][3] = ok1 ? s[m][in][3] : -1e30f;
      }
      float mx0=-1e30f, mx1=-1e30f;
      #pragma unroll
      for(int in=0;in<8;in++){
        mx0 = fmaxf(mx0, fmaxf(s[m][in][0], s[m][in][1]));
        mx1 = fmaxf(mx1, fmaxf(s[m][in][2], s[m][in][3]));
      }
      mx0 = fmaxf(mx0, __shfl_xor_sync(0xffffffffu, mx0, 1));
      mx0 = fmaxf(mx0, __shfl_xor_sync(0xffffffffu, mx0, 2));
      mx1 = fmaxf(mx1, __shfl_xor_sync(0xffffffffu, mx1, 1));
      mx1 = fmaxf(mx1, __shfl_xor_sync(0xffffffffu, mx1, 2));

      float mn0 = fmaxf(mo[2*m], mx0), mn1 = fmaxf(mo[2*m+1], mx1);
      float sc0 = exp2f(mo[2*m] - mn0), sc1 = exp2f(mo[2*m+1] - mn1);

      float rs0=0.f, rs1=0.f;
      #pragma unroll
      for(int in=0;in<8;in++){
        s[m][in][0] = exp2f(s[m][in][0]-mn0); rs0 += s[m][in][0];
        s[m][in][1] = exp2f(s[m][in][1]-mn0); rs0 += s[m][in][1];
        s[m][in][2] = exp2f(s[m][in][2]-mn1); rs1 += s[m][in][2];
        s[m][in][3] = exp2f(s[m][in][3]-mn1); rs1 += s[m][in][3];
      }
      rs0 += __shfl_xor_sync(0xffffffffu, rs0, 1);
      rs0 += __shfl_xor_sync(0xffffffffu, rs0, 2);
      rs1 += __shfl_xor_sync(0xffffffffu, rs1, 1);
      rs1 += __shfl_xor_sync(0xffffffffu, rs1, 2);

      lo[2*m]   = lo[2*m]*sc0 + rs0;
      lo[2*m+1] = lo[2*m+1]*sc1 + rs1;
      mo[2*m] = mn0; mo[2*m+1] = mn1;

      #pragma unroll
      for(int in=0;in<8;in++){
        o[m][in][0]*=sc0; o[m][in][1]*=sc0; o[m][in][2]*=sc1; o[m][in][3]*=sc1;
      }
    }

    #pragma unroll
    for(int kb=0;kb<4;kb++){
      uint32_t ap0[4], ap1[4];
      ap0[0] = h2u(__floats2half2_rn(s[0][2*kb  ][0], s[0][2*kb  ][1]));
      ap0[1] = h2u(__floats2half2_rn(s[0][2*kb  ][2], s[0][2*kb  ][3]));
      ap0[2] = h2u(__floats2half2_rn(s[0][2*kb+1][0], s[0][2*kb+1][1]));
      ap0[3] = h2u(__floats2half2_rn(s[0][2*kb+1][2], s[0][2*kb+1][3]));
      ap1[0] = h2u(__floats2half2_rn(s[1][2*kb  ][0], s[1][2*kb  ][1]));
      ap1[1] = h2u(__floats2half2_rn(s[1][2*kb  ][2], s[1][2*kb  ][3]));
      ap1[2] = h2u(__floats2half2_rn(s[1][2*kb+1][0], s[1][2*kb+1][1]));
      ap1[3] = h2u(__floats2half2_rn(s[1][2*kb+1][2], s[1][2*kb+1][3]));
      #pragma unroll
      for(int p=0;p<4;p++){
        uint32_t b0,b1,b2,b3;
        ldsm4(b0,b1,b2,b3, vab + p*PSTRIDE + kb*32);
        uint32_t bfa[2] = {b0,b1}, bfb[2] = {b2,b3};
        mma_f16(o[0][2*p  ], ap0, bfa);
        mma_f16(o[0][2*p+1], ap0, bfb);
        mma_f16(o[1][2*p  ], ap1, bfa);
        mma_f16(o[1][2*p+1], ap1, bfb);
      }
    }
    __syncthreads();
  }

  #pragma unroll
  for(int m=0;m<2;m++){
    float inv0 = 1.f/lo[2*m], inv1 = 1.f/lo[2*m+1];
    int r0 = q0 + rb + m*16 + g;
    __half* op0 = g_ctx16 + (size_t)(b*L_ + r0    )*D_ + (bh&7)*HD_;
    __half* op1 = g_ctx16 + (size_t)(b*L_ + r0 + 8)*D_ + (bh&7)*HD_;
    #pragma unroll
    for(int in=0;in<8;in++){
      int d = in*8 + tg*2;
      *(__half2*)(op0 + d) = __floats2half2_rn(o[m][in][0]*inv0, o[m][in][1]*inv0);
      *(__half2*)(op1 + d) = __floats2half2_rn(o[m][in][2]*inv1, o[m][in][3]*inv1);
    }
  }
}

// ---------------------------------------------------------------------------
extern "C" void kernel_launch(void* const* d_in, const int* in_sizes, int n_in,
                              void* d_out, int out_size)
{
  (void)in_sizes; (void)n_in; (void)out_size;
  const float* query = (const float*)d_in[0];
  const float* key   = (const float*)d_in[1];
  const float* value = (const float*)d_in[2];
  const int*   mask  = (const int*)d_in[3];
  const float* Wq = (const float*)d_in[4];
  const float* bq = (const float*)d_in[5];
  const float* Wk = (const float*)d_in[6];
  const float* bk = (const float*)d_in[7];
  const float* Wv = (const float*)d_in[8];
  const float* bv = (const float*)d_in[9];
  const float* Wo = (const float*)d_in[10];
  const float* bo = (const float*)d_in[11];
  float* out = (float*)d_out;

  static bool attr_done = false;
  if(!attr_done){
    cudaFuncSetAttribute(gemm_f16,   cudaFuncAttributeMaxDynamicSharedMemorySize, GEMM16_SMEM);
    cudaFuncSetAttribute(flash_attn, cudaFuncAttributeMaxDynamicSharedMemorySize, FLASH_SMEM);
    attr_done = true;
  }

  conv16<<<(int)(MD/4/256), 256>>>(query, key, value, Wq, Wk, Wv, Wo);

  dim3 gq(D_/GBN, M_/GBM, 3);       // (4, 64, 3) — QKV fused
  gemm_f16<<<gq, 256, GEMM16_SMEM>>>(bq, bk, bv, bo, nullptr, 1);

  dim3 fg(L_/FM, B_*H_);            // (32, 16)
  flash_attn<<<fg, FNT, FLASH_SMEM>>>(mask);

  dim3 go(D_/GBN, M_/GBM, 1);       // (4, 64) — output projection
  gemm_f16<<<go, 256, GEMM16_SMEM>>>(bq, bk, bv, bo, out, 4);
}

// round 10
// speedup vs baseline: 1.0173x; 1.0173x over previous
#include <cuda_runtime.h>
#include <cuda_fp16.h>
#include <cstdint>

#define DEVI __device__ __forceinline__

constexpr int B_  = 2;
constexpr int L_  = 4096;
constexpr int D_  = 512;
constexpr int H_  = 8;
constexpr int HD_ = 64;
constexpr int M_  = B_ * L_;          // 8192
constexpr size_t MD = (size_t)M_*D_;  // 4194304
constexpr size_t DD = (size_t)D_*D_;  // 262144

// scratch: __device__ globals (allocation-free rule)
__device__ __half g_x16[3*MD];          // fp16 copies of query,key,value
__device__ __half g_w16[4*DD];          // fp16 copies of Wq,Wk,Wv,Wo
__device__ __half g_qh[B_*H_*L_*HD_];   // [b,h,l,d] (pre-scaled by 0.125*log2e)
__device__ __half g_kh[B_*H_*L_*HD_];   // [b,h,l,d]
__device__ __half g_vt[B_*H_*HD_*L_];   // [b,h,d,l]  (transposed)
__device__ __half g_ctx16[MD];          // attention output, fp16
__device__ int    g_mflag[B_*64];       // 1 if 64-key block fully valid

DEVI uint32_t h2u(__half2 h){ union{ __half2 h; uint32_t u; } c; c.h = h; return c.u; }

DEVI void mma_f16(float* c, const uint32_t* a, const uint32_t* b){
  asm volatile("mma.sync.aligned.m16n8k16.row.col.f32.f16.f16.f32 "
    "{%0,%1,%2,%3},{%4,%5,%6,%7},{%8,%9},{%0,%1,%2,%3};\n"
    : "+f"(c[0]),"+f"(c[1]),"+f"(c[2]),"+f"(c[3])
    : "r"(a[0]),"r"(a[1]),"r"(a[2]),"r"(a[3]),"r"(b[0]),"r"(b[1]));
}

DEVI void ldsm4(uint32_t& r0, uint32_t& r1, uint32_t& r2, uint32_t& r3, uint32_t addr){
  asm volatile("ldmatrix.sync.aligned.m8n8.x4.shared.b16 {%0,%1,%2,%3}, [%4];"
    : "=r"(r0),"=r"(r1),"=r"(r2),"=r"(r3) : "r"(addr));
}
DEVI void ldsm4t(uint32_t& r0, uint32_t& r1, uint32_t& r2, uint32_t& r3, uint32_t addr){
  asm volatile("ldmatrix.sync.aligned.m8n8.x4.trans.shared.b16 {%0,%1,%2,%3}, [%4];"
    : "=r"(r0),"=r"(r1),"=r"(r2),"=r"(r3) : "r"(addr));
}

DEVI void cpa16(void* s, const void* g){
  uint32_t sa = (uint32_t)__cvta_generic_to_shared(s);
  asm volatile("cp.async.cg.shared.global [%0], [%1], 16;\n"::"r"(sa),"l"(g));
}
DEVI void cpa_commit(){ asm volatile("cp.async.commit_group;\n"); }
template<int N> DEVI void cpa_wait(){ asm volatile("cp.async.wait_group %0;\n"::"n"(N)); }

// ---------------------------------------------------------------------------
// conv16: round inputs + weights to fp16 once; also mask block flags
// ---------------------------------------------------------------------------
__global__ void conv16(const float* __restrict__ q, const float* __restrict__ k,
                       const float* __restrict__ v,
                       const float* __restrict__ wq, const float* __restrict__ wk,
                       const float* __restrict__ wv, const float* __restrict__ wo,
                       const int* __restrict__ mask)
{
  size_t i = ((size_t)blockIdx.x*blockDim.x + threadIdx.x)*4;
  if(i < MD){
    float4 a;
    a = *(const float4*)(q+i);
    *(__half2*)(g_x16 + i)        = __floats2half2_rn(a.x,a.y);
    *(__half2*)(g_x16 + i + 2)    = __floats2half2_rn(a.z,a.w);
    a = *(const float4*)(k+i);
    *(__half2*)(g_x16 + MD + i)   = __floats2half2_rn(a.x,a.y);
    *(__half2*)(g_x16 + MD + i+2) = __floats2half2_rn(a.z,a.w);
    a = *(const float4*)(v+i);
    *(__half2*)(g_x16 + 2*MD + i)   = __floats2half2_rn(a.x,a.y);
    *(__half2*)(g_x16 + 2*MD + i+2) = __floats2half2_rn(a.z,a.w);
  }
  if(i < DD){
    float4 a;
    a = *(const float4*)(wq+i);
    *(__half2*)(g_w16 + i)        = __floats2half2_rn(a.x,a.y);
    *(__half2*)(g_w16 + i + 2)    = __floats2half2_rn(a.z,a.w);
    a = *(const float4*)(wk+i);
    *(__half2*)(g_w16 + DD + i)   = __floats2half2_rn(a.x,a.y);
    *(__half2*)(g_w16 + DD + i+2) = __floats2half2_rn(a.z,a.w);
    a = *(const float4*)(wv+i);
    *(__half2*)(g_w16 + 2*DD + i)   = __floats2half2_rn(a.x,a.y);
    *(__half2*)(g_w16 + 2*DD + i+2) = __floats2half2_rn(a.z,a.w);
    a = *(const float4*)(wo+i);
    *(__half2*)(g_w16 + 3*DD + i)   = __floats2half2_rn(a.x,a.y);
    *(__half2*)(g_w16 + 3*DD + i+2) = __floats2half2_rn(a.z,a.w);
  }
  if(blockIdx.x == 0 && threadIdx.x < B_*64){
    int b = threadIdx.x >> 6, t = threadIdx.x & 63;
    const int* mp = mask + b*L_ + t*64;
    int ok = 1;
    #pragma unroll 8
    for(int j=0;j<64;j++) ok &= (mp[j]!=0);
    g_mflag[threadIdx.x] = ok;
  }
}

// ---------------------------------------------------------------------------
// fp16 GEMM: C[M,512] = A[M,512] @ W[512,512] + bias   (fp32 accum)
// ---------------------------------------------------------------------------
constexpr int GBM = 128, GBN = 128, GBK = 64;
constexpr int GAW = 36;
constexpr int GBW = 68;
constexpr int GA_WORDS = GBM*GAW;   // 4608
constexpr int GB_WORDS = GBK*GBW;   // 4352
constexpr int GEMM16_SMEM = (2*GA_WORDS + 2*GB_WORDS)*4;   // 71680

__global__ void __launch_bounds__(256,2) gemm_f16(
  const float* __restrict__ bq, const float* __restrict__ bk,
  const float* __restrict__ bv, const float* __restrict__ bo,
  float* __restrict__ out, int mode_base)
{
  extern __shared__ uint32_t smw[];
  uint32_t* Aw = smw;
  uint32_t* Bw = smw + 2*GA_WORDS;

  int mode = mode_base + blockIdx.z;     // 1..3 or 4
  const __half* A = (mode==4) ? g_ctx16 : g_x16 + (size_t)(mode-1)*MD;
  const __half* W = g_w16 + (size_t)(mode-1)*DD;
  const float* bias = (mode==1)?bq : (mode==2)?bk : (mode==3)?bv : bo;

  int tid = threadIdx.x;
  int m0 = blockIdx.y*GBM, n0 = blockIdx.x*GBN;
  int w = tid>>5, lane = tid&31, g = lane>>2, tg = lane&3;
  int wm = (w>>1)*32, wn = (w&1)*64;

  uint32_t sbase = (uint32_t)__cvta_generic_to_shared(smw);
  int t8  = lane & 7;
  int lb1 = (lane>>3) & 1;
  int lb2 = lane>>4;
  uint32_t a0 = sbase + (uint32_t)((wm      + lb1*8 + t8)*GAW + lb2*4)*4;
  uint32_t a1 = sbase + (uint32_t)((wm + 16 + lb1*8 + t8)*GAW + lb2*4)*4;
  uint32_t bb = sbase + (uint32_t)(2*GA_WORDS)*4
              + (uint32_t)((lb1*8 + t8)*GBW)*4 + (uint32_t)(wn + lb2*8)*2;
  constexpr uint32_t ABUF = GA_WORDS*4, BBUF = GB_WORDS*4;
  constexpr uint32_t BKSTEP = 16*GBW*4;

  float acc[2][8][4];
  #pragma unroll
  for(int i=0;i<2;i++)
    #pragma unroll
    for(int j=0;j<8;j++)
      #pragma unroll
      for(int k2=0;k2<4;k2++) acc[i][j][k2]=0.f;

  auto load_tiles = [&](int buf, int kt){
    const __half* ga = A + (size_t)m0*D_ + kt*GBK;
    #pragma unroll
    for(int j=0;j<4;j++){
      int idx = tid + j*256;
      int r = idx>>3, c = idx&7;
      cpa16((char*)(Aw + buf*GA_WORDS + r*GAW) + c*16, ga + (size_t)r*D_ + c*8);
    }
    const __half* gb = W + (size_t)(kt*GBK)*D_ + n0;
    #pragma unroll
    for(int j=0;j<4;j++){
      int idx = tid + j*256;
      int r = idx>>4, c = idx&15;
      cpa16((char*)(Bw + buf*GB_WORDS + r*GBW) + c*16, gb + (size_t)r*D_ + c*8);
    }
  };

  load_tiles(0,0); cpa_commit();

  #pragma unroll 1
  for(int kt=0; kt<D_/GBK; kt++){
    if(kt+1 < D_/GBK){ load_tiles((kt+1)&1, kt+1); cpa_commit(); cpa_wait<1>(); }
    else             { cpa_wait<0>(); }
    __syncthreads();
    int buf = kt&1;
    uint32_t ac0 = a0 + buf*ABUF, ac1 = a1 + buf*ABUF;
    uint32_t bc  = bb + buf*BBUF;
    #pragma unroll
    for(int kk=0; kk<4; kk++){
      uint32_t af0[4], af1[4];
      ldsm4(af0[0],af0[1],af0[2],af0[3], ac0 + kk*32);
      ldsm4(af1[0],af1[1],af1[2],af1[3], ac1 + kk*32);
      #pragma unroll
      for(int j=0;j<4;j++){
        uint32_t b0,b1,b2,b3;
        ldsm4t(b0,b1,b2,b3, bc + kk*BKSTEP + j*32);
        uint32_t bfa[2] = {b0,b1}, bfb[2] = {b2,b3};
        mma_f16(acc[0][2*j  ], af0, bfa);
        mma_f16(acc[0][2*j+1], af0, bfb);
        mma_f16(acc[1][2*j  ], af1, bfa);
        mma_f16(acc[1][2*j+1], af1, bfb);
      }
    }
    __syncthreads();
  }

  float oscale = (mode==1) ? 0.125f*1.44269504f : 1.0f;
  #pragma unroll
  for(int im=0;im<2;im++){
    int r0 = m0 + wm + im*16 + g;
    int r8 = r0 + 8;
    #pragma unroll
    for(int in=0;in<8;in++){
      int col = n0 + wn + in*8 + tg*2;
      float bx = bias[col], by = bias[col+1];
      float2 v0 = make_float2(acc[im][in][0]+bx, acc[im][in][1]+by);
      float2 v1 = make_float2(acc[im][in][2]+bx, acc[im][in][3]+by);
      if(mode==4){
        *(float2*)(out + (size_t)r0*D_ + col) = v0;
        *(float2*)(out + (size_t)r8*D_ + col) = v1;
      } else {
        int h = col>>6, d = col&63;
        int b0i = r0>>12, t0 = r0&4095;
        int b1i = r8>>12, t1 = r8&4095;
        if(mode==3){
          size_t i0 = ((size_t)(b0i*H_ + h)*HD_ + d)*L_ + t0;
          size_t i1 = ((size_t)(b1i*H_ + h)*HD_ + d)*L_ + t1;
          g_vt[i0]      = __float2half_rn(v0.x);
          g_vt[i0 + L_] = __float2half_rn(v0.y);
          g_vt[i1]      = __float2half_rn(v1.x);
          g_vt[i1 + L_] = __float2half_rn(v1.y);
        } else {
          __half* C = (mode==1) ? g_qh : g_kh;
          size_t i0 = ((size_t)(b0i*H_ + h)*L_ + t0)*HD_ + d;
          size_t i1 = ((size_t)(b1i*H_ + h)*L_ + t1)*HD_ + d;
          *(__half2*)(C + i0) = __floats2half2_rn(v0.x*oscale, v0.y*oscale);
          *(__half2*)(C + i1) = __floats2half2_rn(v1.x*oscale, v1.y*oscale);
        }
      }
    }
  }
}

// ---------------------------------------------------------------------------
// Flash attention: 8 warps x 32 q-rows (FM=256), Q frags in registers.
// 4-stage KV ring, prefetch distance 2, ONE barrier per tile (warps may skew
// up to a full tile -> softmax of one warp overlaps MMAs of another).
// Skip-rescale branch + mask-allones fast path. exp2-domain softmax.
// ---------------------------------------------------------------------------
constexpr int FM = 256, FN = 64, NST = 4;
constexpr int RSW = 36;
constexpr int Q_WORDS = FM*RSW;         // 9216
constexpr int K_WORDS = FN*RSW;         // 2304
constexpr int V_WORDS = FN*RSW;         // 2304
constexpr int NTILES = L_/FN;           // 64
constexpr int FLASH_SMEM = (Q_WORDS + NST*K_WORDS + NST*V_WORDS)*4 + NST*FN*4;

__global__ void __launch_bounds__(256,1) flash_attn(const int* __restrict__ mask)
{
  extern __shared__ uint32_t smw[];
  uint32_t* Qw = smw;                     // [256][36]
  uint32_t* Kw = smw + Q_WORDS;           // [NST][64][36]
  uint32_t* Vw = Kw + NST*K_WORDS;        // [NST][64][36]
  int*      Ms = (int*)(Vw + NST*V_WORDS);

  int tid = threadIdx.x, w = tid>>5, lane = tid&31, g = lane>>2, tg = lane&3;
  int bh = blockIdx.y;
  int b  = bh >> 3;
  int q0 = blockIdx.x * FM;
  int rb = w*32;

  const __half* Qg = g_qh + (size_t)bh*L_*HD_ + (size_t)q0*HD_;
  const __half* Kg = g_kh + (size_t)bh*L_*HD_;
  const __half* Vg = g_vt + (size_t)bh*HD_*L_;
  const int*    mg = mask + b*L_;
  const int*    mf = g_mflag + b*64;

  uint32_t smem_base = (uint32_t)__cvta_generic_to_shared(smw);
  int t8  = lane & 7;
  int lb1 = (lane>>3) & 1;
  int lb2 = lane>>4;
  uint32_t qaddr0 = smem_base + (uint32_t)((rb      + lb1*8 + t8)*RSW + lb2*4)*4;
  uint32_t qaddr1 = smem_base + (uint32_t)((rb + 16 + lb1*8 + t8)*RSW + lb2*4)*4;
  uint32_t kvoff = (uint32_t)(((lb2*8 + t8)*RSW) + lb1*4)*4;
  uint32_t kbase = smem_base + (uint32_t)Q_WORDS*4 + kvoff;
  uint32_t vbase = smem_base + (uint32_t)(Q_WORDS + NST*K_WORDS)*4 + kvoff;
  constexpr uint32_t PSTRIDE = 16*RSW*4;
  constexpr uint32_t KBUF = K_WORDS*4, VBUF = V_WORDS*4;

  // Q tile: 256 rows x 8 chunks
  #pragma unroll
  for(int j=0;j<8;j++){
    int idx = tid + j*256;
    int r = idx>>3, c = idx&7;
    cpa16((char*)(Qw + r*RSW) + c*16, Qg + (size_t)r*HD_ + c*8);
  }
  cpa_commit();

  auto loadKV = [&](int st, int it){
    const __half* kg = Kg + (size_t)it*FN*HD_;
    const __half* vg = Vg + it*FN;
    #pragma unroll
    for(int j=0;j<2;j++){
      int idx = tid + j*256;
      int r = idx>>3, c = idx&7;
      cpa16((char*)(Kw + st*K_WORDS + r*RSW) + c*16, kg + (size_t)r*HD_ + c*8);
    }
    #pragma unroll
    for(int j=0;j<2;j++){
      int idx = tid + j*256;
      int r = idx>>3, c = idx&7;
      cpa16((char*)(Vw + st*V_WORDS + r*RSW) + c*16, vg + (size_t)r*L_ + c*8);
    }
    if(tid < 16) cpa16(&Ms[st*FN + tid*4], mg + it*FN + tid*4);
  };

  // Q -> registers (loop invariant)
  cpa_wait<0>();
  __syncthreads();
  uint32_t qf[2][4][4];
  #pragma unroll
  for(int kk=0;kk<4;kk++){
    ldsm4(qf[0][kk][0],qf[0][kk][1],qf[0][kk][2],qf[0][kk][3], qaddr0 + kk*32);
    ldsm4(qf[1][kk][0],qf[1][kk][1],qf[1][kk][2],qf[1][kk][3], qaddr1 + kk*32);
  }

  loadKV(0,0); cpa_commit();
  loadKV(1,1); cpa_commit();

  float o[2][8][4];
  #pragma unroll
  for(int m=0;m<2;m++)
    #pragma unroll
    for(int i=0;i<8;i++)
      #pragma unroll
      for(int j=0;j<4;j++) o[m][i][j]=0.f;
  float mo[4] = {-1e30f,-1e30f,-1e30f,-1e30f};
  float lo[4] = {0.f,0.f,0.f,0.f};

  #pragma unroll 1
  for(int it=0; it<NTILES; it++){
    if(it+2 < NTILES){ loadKV((it+2)&(NST-1), it+2); cpa_commit(); cpa_wait<2>(); }
    else             { cpa_wait<0>(); }
    __syncthreads();                       // single barrier per tile

    int st = it&(NST-1);
    uint32_t kab = kbase + st*KBUF;
    uint32_t vab = vbase + st*VBUF;
    const int* ms = Ms + st*FN;
    int mflag = mf[it];                    // 1 = whole 64-key block valid

    float s[2][8][4];
    #pragma unroll
    for(int m=0;m<2;m++)
      #pragma unroll
      for(int i=0;i<8;i++)
        #pragma unroll
        for(int j=0;j<4;j++) s[m][i][j]=0.f;

    #pragma unroll
    for(int kk=0; kk<4; kk++){
      #pragma unroll
      for(int p=0;p<4;p++){
        uint32_t b0,b1,b2,b3;
        ldsm4(b0,b1,b2,b3, kab + p*PSTRIDE + kk*32);
        uint32_t bfa[2] = {b0,b1}, bfb[2] = {b2,b3};
        mma_f16(s[0][2*p  ], qf[0][kk], bfa);
        mma_f16(s[0][2*p+1], qf[0][kk], bfb);
        mma_f16(s[1][2*p  ], qf[1][kk], bfa);
        mma_f16(s[1][2*p+1], qf[1][kk], bfb);
      }
    }

    if(!mflag){
      #pragma unroll
      for(int m=0;m<2;m++)
        #pragma unroll
        for(int in=0;in<8;in++){
          int c0 = in*8 + tg*2;
          bool ok0 = ms[c0]!=0, ok1 = ms[c0+1]!=0;
          s[m][in][0] = ok0 ? s[m][in][0] : -1e30f;
          s[m][in][1] = ok1 ? s[m][in][1] : -1e30f;
          s[m][in][2] = ok0 ? s[m][in][2] : -1e30f;
          s[m][in][3] = ok1 ? s[m][in][3] : -1e30f;
        }
    }

    #pragma unroll
    for(int m=0;m<2;m++){
      float mx0=-1e30f, mx1=-1e30f;
      #pragma unroll
      for(int in=0;in<8;in++){
        mx0 = fmaxf(mx0, fmaxf(s[m][in][0], s[m][in][1]));
        mx1 = fmaxf(mx1, fmaxf(s[m][in][2], s[m][in][3]));
      }
      mx0 = fmaxf(mx0, __shfl_xor_sync(0xffffffffu, mx0, 1));
      mx0 = fmaxf(mx0, __shfl_xor_sync(0xffffffffu, mx0, 2));
      mx1 = fmaxf(mx1, __shfl_xor_sync(0xffffffffu, mx1, 1));
      mx1 = fmaxf(mx1, __shfl_xor_sync(0xffffffffu, mx1, 2));

      float mn0, mn1;
      bool up = (mx0 > mo[2*m]) || (mx1 > mo[2*m+1]);
      if(__any_sync(0xffffffffu, up)){
        mn0 = fmaxf(mo[2*m], mx0); mn1 = fmaxf(mo[2*m+1], mx1);
        float sc0 = exp2f(mo[2*m] - mn0), sc1 = exp2f(mo[2*m+1] - mn1);
        lo[2*m] *= sc0; lo[2*m+1] *= sc1;
        mo[2*m] = mn0;  mo[2*m+1] = mn1;
        #pragma unroll
        for(int in=0;in<8;in++){
          o[m][in][0]*=sc0; o[m][in][1]*=sc0; o[m][in][2]*=sc1; o[m][in][3]*=sc1;
        }
      } else {
        mn0 = mo[2*m]; mn1 = mo[2*m+1];   // sc==1 exactly: skip rescale
      }

      float rs0=0.f, rs1=0.f;
      #pragma unroll
      for(int in=0;in<8;in++){
        s[m][in][0] = exp2f(s[m][in][0]-mn0); rs0 += s[m][in][0];
        s[m][in][1] = exp2f(s[m][in][1]-mn0); rs0 += s[m][in][1];
        s[m][in][2] = exp2f(s[m][in][2]-mn1); rs1 += s[m][in][2];
        s[m][in][3] = exp2f(s[m][in][3]-mn1); rs1 += s[m][in][3];
      }
      rs0 += __shfl_xor_sync(0xffffffffu, rs0, 1);
      rs0 += __shfl_xor_sync(0xffffffffu, rs0, 2);
      rs1 += __shfl_xor_sync(0xffffffffu, rs1, 1);
      rs1 += __shfl_xor_sync(0xffffffffu, rs1, 2);

      lo[2*m]   += rs0;
      lo[2*m+1] += rs1;
    }

    #pragma unroll
    for(int kb=0;kb<4;kb++){
      uint32_t ap0[4], ap1[4];
      ap0[0] = h2u(__floats2half2_rn(s[0][2*kb  ][0], s[0][2*kb  ][1]));
      ap0[1] = h2u(__floats2half2_rn(s[0][2*kb  ][2], s[0][2*kb  ][3]));
      ap0[2] = h2u(__floats2half2_rn(s[0][2*kb+1][0], s[0][2*kb+1][1]));
      ap0[3] = h2u(__floats2half2_rn(s[0][2*kb+1][2], s[0][2*kb+1][3]));
      ap1[0] = h2u(__floats2half2_rn(s[1][2*kb  ][0], s[1][2*kb  ][1]));
      ap1[1] = h2u(__floats2half2_rn(s[1][2*kb  ][2], s[1][2*kb  ][3]));
      ap1[2] = h2u(__floats2half2_rn(s[1][2*kb+1][0], s[1][2*kb+1][1]));
      ap1[3] = h2u(__floats2half2_rn(s[1][2*kb+1][2], s[1][2*kb+1][3]));
      #pragma unroll
      for(int p=0;p<4;p++){
        uint32_t b0,b1,b2,b3;
        ldsm4(b0,b1,b2,b3, vab + p*PSTRIDE + kb*32);
        uint32_t bfa[2] = {b0,b1}, bfb[2] = {b2,b3};
        mma_f16(o[0][2*p  ], ap0, bfa);
        mma_f16(o[0][2*p+1], ap0, bfb);
        mma_f16(o[1][2*p  ], ap1, bfa);
        mma_f16(o[1][2*p+1], ap1, bfb);
      }
    }
    // no trailing barrier: 4-stage ring tolerates 1 full tile of warp skew
  }

  #pragma unroll
  for(int m=0;m<2;m++){
    float inv0 = 1.f/lo[2*m], inv1 = 1.f/lo[2*m+1];
    int r0 = q0 + rb + m*16 + g;
    __half* op0 = g_ctx16 + (size_t)(b*L_ + r0    )*D_ + (bh&7)*HD_;
    __half* op1 = g_ctx16 + (size_t)(b*L_ + r0 + 8)*D_ + (bh&7)*HD_;
    #pragma unroll
    for(int in=0;in<8;in++){
      int d = in*8 + tg*2;
      *(__half2*)(op0 + d) = __floats2half2_rn(o[m][in][0]*inv0, o[m][in][1]*inv0);
      *(__half2*)(op1 + d) = __floats2half2_rn(o[m][in][2]*inv1, o[m][in][3]*inv1);
    }
  }
}

// ---------------------------------------------------------------------------
extern "C" void kernel_launch(void* const* d_in, const int* in_sizes, int n_in,
                              void* d_out, int out_size)
{
  (void)in_sizes; (void)n_in; (void)out_size;
  const float* query = (const float*)d_in[0];
  const float* key   = (const float*)d_in[1];
  const float* value = (const float*)d_in[2];
  const int*   mask  = (const int*)d_in[3];
  const float* Wq = (const float*)d_in[4];
  const float* bq = (const float*)d_in[5];
  const float* Wk = (const float*)d_in[6];
  const float* bk = (const float*)d_in[7];
  const float* Wv = (const float*)d_in[8];
  const float* bv = (const float*)d_in[9];
  const float* Wo = (const float*)d_in[10];
  const float* bo = (const float*)d_in[11];
  float* out = (float*)d_out;

  static bool attr_done = false;
  if(!attr_done){
    cudaFuncSetAttribute(gemm_f16,   cudaFuncAttributeMaxDynamicSharedMemorySize, GEMM16_SMEM);
    cudaFuncSetAttribute(flash_attn, cudaFuncAttributeMaxDynamicSharedMemorySize, FLASH_SMEM);
    attr_done = true;
  }

  conv16<<<(int)(MD/4/256), 256>>>(query, key, value, Wq, Wk, Wv, Wo, mask);

  dim3 gq(D_/GBN, M_/GBM, 3);       // (4, 64, 3) — QKV fused
  gemm_f16<<<gq, 256, GEMM16_SMEM>>>(bq, bk, bv, bo, nullptr, 1);

  dim3 fg(L_/FM, B_*H_);            // (16, 16)
  flash_attn<<<fg, 256, FLASH_SMEM>>>(mask);

  dim3 go(D_/GBN, M_/GBM, 1);       // (4, 64) — output projection
  gemm_f16<<<go, 256, GEMM16_SMEM>>>(bq, bk, bv, bo, out, 4);
}

// round 11
// speedup vs baseline: 1.0392x; 1.0216x over previous
#include <cuda_runtime.h>
#include <cuda_fp16.h>
#include <cstdint>

#define DEVI __device__ __forceinline__

constexpr int B_  = 2;
constexpr int L_  = 4096;
constexpr int D_  = 512;
constexpr int H_  = 8;
constexpr int HD_ = 64;
constexpr int M_  = B_ * L_;          // 8192
constexpr size_t MD = (size_t)M_*D_;  // 4194304
constexpr size_t DD = (size_t)D_*D_;  // 262144

// scratch: __device__ globals (allocation-free rule)
__device__ __half g_x16[3*MD];          // fp16 copies of query,key,value
__device__ __half g_w16[4*DD];          // fp16 copies of Wq,Wk,Wv,Wo
__device__ __half g_qh[B_*H_*L_*HD_];   // [b,h,l,d] (pre-scaled by 0.125*log2e)
__device__ __half g_kh[B_*H_*L_*HD_];   // [b,h,l,d]
__device__ __half g_vt[B_*H_*HD_*L_];   // [b,h,d,l]  (transposed)
__device__ __half g_ctx16[MD];          // attention output, fp16
__device__ int    g_mflag[B_*64];       // 1 if 64-key block fully valid

DEVI uint32_t h2u(__half2 h){ union{ __half2 h; uint32_t u; } c; c.h = h; return c.u; }

DEVI void mma_f16(float* c, const uint32_t* a, const uint32_t* b){
  asm volatile("mma.sync.aligned.m16n8k16.row.col.f32.f16.f16.f32 "
    "{%0,%1,%2,%3},{%4,%5,%6,%7},{%8,%9},{%0,%1,%2,%3};\n"
    : "+f"(c[0]),"+f"(c[1]),"+f"(c[2]),"+f"(c[3])
    : "r"(a[0]),"r"(a[1]),"r"(a[2]),"r"(a[3]),"r"(b[0]),"r"(b[1]));
}

DEVI uint32_t ex2h2(uint32_t x){
  uint32_t r;
  asm("ex2.approx.f16x2 %0, %1;" : "=r"(r) : "r"(x));
  return r;
}

DEVI void ldsm4(uint32_t& r0, uint32_t& r1, uint32_t& r2, uint32_t& r3, uint32_t addr){
  asm volatile("ldmatrix.sync.aligned.m8n8.x4.shared.b16 {%0,%1,%2,%3}, [%4];"
    : "=r"(r0),"=r"(r1),"=r"(r2),"=r"(r3) : "r"(addr));
}
DEVI void ldsm4t(uint32_t& r0, uint32_t& r1, uint32_t& r2, uint32_t& r3, uint32_t addr){
  asm volatile("ldmatrix.sync.aligned.m8n8.x4.trans.shared.b16 {%0,%1,%2,%3}, [%4];"
    : "=r"(r0),"=r"(r1),"=r"(r2),"=r"(r3) : "r"(addr));
}

DEVI void cpa16(void* s, const void* g){
  uint32_t sa = (uint32_t)__cvta_generic_to_shared(s);
  asm volatile("cp.async.cg.shared.global [%0], [%1], 16;\n"::"r"(sa),"l"(g));
}
DEVI void cpa_commit(){ asm volatile("cp.async.commit_group;\n"); }
template<int N> DEVI void cpa_wait(){ asm volatile("cp.async.wait_group %0;\n"::"n"(N)); }

// ---------------------------------------------------------------------------
// conv16: round inputs + weights to fp16 once; also mask block flags
// ---------------------------------------------------------------------------
__global__ void conv16(const float* __restrict__ q, const float* __restrict__ k,
                       const float* __restrict__ v,
                       const float* __restrict__ wq, const float* __restrict__ wk,
                       const float* __restrict__ wv, const float* __restrict__ wo,
                       const int* __restrict__ mask)
{
  size_t i = ((size_t)blockIdx.x*blockDim.x + threadIdx.x)*4;
  if(i < MD){
    float4 a;
    a = *(const float4*)(q+i);
    *(__half2*)(g_x16 + i)        = __floats2half2_rn(a.x,a.y);
    *(__half2*)(g_x16 + i + 2)    = __floats2half2_rn(a.z,a.w);
    a = *(const float4*)(k+i);
    *(__half2*)(g_x16 + MD + i)   = __floats2half2_rn(a.x,a.y);
    *(__half2*)(g_x16 + MD + i+2) = __floats2half2_rn(a.z,a.w);
    a = *(const float4*)(v+i);
    *(__half2*)(g_x16 + 2*MD + i)   = __floats2half2_rn(a.x,a.y);
    *(__half2*)(g_x16 + 2*MD + i+2) = __floats2half2_rn(a.z,a.w);
  }
  if(i < DD){
    float4 a;
    a = *(const float4*)(wq+i);
    *(__half2*)(g_w16 + i)        = __floats2half2_rn(a.x,a.y);
    *(__half2*)(g_w16 + i + 2)    = __floats2half2_rn(a.z,a.w);
    a = *(const float4*)(wk+i);
    *(__half2*)(g_w16 + DD + i)   = __floats2half2_rn(a.x,a.y);
    *(__half2*)(g_w16 + DD + i+2) = __floats2half2_rn(a.z,a.w);
    a = *(const float4*)(wv+i);
    *(__half2*)(g_w16 + 2*DD + i)   = __floats2half2_rn(a.x,a.y);
    *(__half2*)(g_w16 + 2*DD + i+2) = __floats2half2_rn(a.z,a.w);
    a = *(const float4*)(wo+i);
    *(__half2*)(g_w16 + 3*DD + i)   = __floats2half2_rn(a.x,a.y);
    *(__half2*)(g_w16 + 3*DD + i+2) = __floats2half2_rn(a.z,a.w);
  }
  if(blockIdx.x == 0 && threadIdx.x < B_*64){
    int b = threadIdx.x >> 6, t = threadIdx.x & 63;
    const int* mp = mask + b*L_ + t*64;
    int ok = 1;
    #pragma unroll 8
    for(int j=0;j<64;j++) ok &= (mp[j]!=0);
    g_mflag[threadIdx.x] = ok;
  }
}

// ---------------------------------------------------------------------------
// fp16 GEMM: C[M,512] = A[M,512] @ W[512,512] + bias   (fp32 accum)
// ---------------------------------------------------------------------------
constexpr int GBM = 128, GBN = 128, GBK = 64;
constexpr int GAW = 36;
constexpr int GBW = 68;
constexpr int GA_WORDS = GBM*GAW;   // 4608
constexpr int GB_WORDS = GBK*GBW;   // 4352
constexpr int GEMM16_SMEM = (2*GA_WORDS + 2*GB_WORDS)*4;   // 71680

__global__ void __launch_bounds__(256,2) gemm_f16(
  const float* __restrict__ bq, const float* __restrict__ bk,
  const float* __restrict__ bv, const float* __restrict__ bo,
  float* __restrict__ out, int mode_base)
{
  extern __shared__ uint32_t smw[];
  uint32_t* Aw = smw;
  uint32_t* Bw = smw + 2*GA_WORDS;

  int mode = mode_base + blockIdx.z;     // 1..3 or 4
  const __half* A = (mode==4) ? g_ctx16 : g_x16 + (size_t)(mode-1)*MD;
  const __half* W = g_w16 + (size_t)(mode-1)*DD;
  const float* bias = (mode==1)?bq : (mode==2)?bk : (mode==3)?bv : bo;

  int tid = threadIdx.x;
  int m0 = blockIdx.y*GBM, n0 = blockIdx.x*GBN;
  int w = tid>>5, lane = tid&31, g = lane>>2, tg = lane&3;
  int wm = (w>>1)*32, wn = (w&1)*64;

  uint32_t sbase = (uint32_t)__cvta_generic_to_shared(smw);
  int t8  = lane & 7;
  int lb1 = (lane>>3) & 1;
  int lb2 = lane>>4;
  uint32_t a0 = sbase + (uint32_t)((wm      + lb1*8 + t8)*GAW + lb2*4)*4;
  uint32_t a1 = sbase + (uint32_t)((wm + 16 + lb1*8 + t8)*GAW + lb2*4)*4;
  uint32_t bb = sbase + (uint32_t)(2*GA_WORDS)*4
              + (uint32_t)((lb1*8 + t8)*GBW)*4 + (uint32_t)(wn + lb2*8)*2;
  constexpr uint32_t ABUF = GA_WORDS*4, BBUF = GB_WORDS*4;
  constexpr uint32_t BKSTEP = 16*GBW*4;

  float acc[2][8][4];
  #pragma unroll
  for(int i=0;i<2;i++)
    #pragma unroll
    for(int j=0;j<8;j++)
      #pragma unroll
      for(int k2=0;k2<4;k2++) acc[i][j][k2]=0.f;

  auto load_tiles = [&](int buf, int kt){
    const __half* ga = A + (size_t)m0*D_ + kt*GBK;
    #pragma unroll
    for(int j=0;j<4;j++){
      int idx = tid + j*256;
      int r = idx>>3, c = idx&7;
      cpa16((char*)(Aw + buf*GA_WORDS + r*GAW) + c*16, ga + (size_t)r*D_ + c*8);
    }
    const __half* gb = W + (size_t)(kt*GBK)*D_ + n0;
    #pragma unroll
    for(int j=0;j<4;j++){
      int idx = tid + j*256;
      int r = idx>>4, c = idx&15;
      cpa16((char*)(Bw + buf*GB_WORDS + r*GBW) + c*16, gb + (size_t)r*D_ + c*8);
    }
  };

  load_tiles(0,0); cpa_commit();

  #pragma unroll 1
  for(int kt=0; kt<D_/GBK; kt++){
    if(kt+1 < D_/GBK){ load_tiles((kt+1)&1, kt+1); cpa_commit(); cpa_wait<1>(); }
    else             { cpa_wait<0>(); }
    __syncthreads();
    int buf = kt&1;
    uint32_t ac0 = a0 + buf*ABUF, ac1 = a1 + buf*ABUF;
    uint32_t bc  = bb + buf*BBUF;
    #pragma unroll
    for(int kk=0; kk<4; kk++){
      uint32_t af0[4], af1[4];
      ldsm4(af0[0],af0[1],af0[2],af0[3], ac0 + kk*32);
      ldsm4(af1[0],af1[1],af1[2],af1[3], ac1 + kk*32);
      #pragma unroll
      for(int j=0;j<4;j++){
        uint32_t b0,b1,b2,b3;
        ldsm4t(b0,b1,b2,b3, bc + kk*BKSTEP + j*32);
        uint32_t bfa[2] = {b0,b1}, bfb[2] = {b2,b3};
        mma_f16(acc[0][2*j  ], af0, bfa);
        mma_f16(acc[0][2*j+1], af0, bfb);
        mma_f16(acc[1][2*j  ], af1, bfa);
        mma_f16(acc[1][2*j+1], af1, bfb);
      }
    }
    __syncthreads();
  }

  float oscale = (mode==1) ? 0.125f*1.44269504f : 1.0f;
  #pragma unroll
  for(int im=0;im<2;im++){
    int r0 = m0 + wm + im*16 + g;
    int r8 = r0 + 8;
    #pragma unroll
    for(int in=0;in<8;in++){
      int col = n0 + wn + in*8 + tg*2;
      float bx = bias[col], by = bias[col+1];
      float2 v0 = make_float2(acc[im][in][0]+bx, acc[im][in][1]+by);
      float2 v1 = make_float2(acc[im][in][2]+bx, acc[im][in][3]+by);
      if(mode==4){
        *(float2*)(out + (size_t)r0*D_ + col) = v0;
        *(float2*)(out + (size_t)r8*D_ + col) = v1;
      } else {
        int h = col>>6, d = col&63;
        int b0i = r0>>12, t0 = r0&4095;
        int b1i = r8>>12, t1 = r8&4095;
        if(mode==3){
          size_t i0 = ((size_t)(b0i*H_ + h)*HD_ + d)*L_ + t0;
          size_t i1 = ((size_t)(b1i*H_ + h)*HD_ + d)*L_ + t1;
          g_vt[i0]      = __float2half_rn(v0.x);
          g_vt[i0 + L_] = __float2half_rn(v0.y);
          g_vt[i1]      = __float2half_rn(v1.x);
          g_vt[i1 + L_] = __float2half_rn(v1.y);
        } else {
          __half* C = (mode==1) ? g_qh : g_kh;
          size_t i0 = ((size_t)(b0i*H_ + h)*L_ + t0)*HD_ + d;
          size_t i1 = ((size_t)(b1i*H_ + h)*L_ + t1)*HD_ + d;
          *(__half2*)(C + i0) = __floats2half2_rn(v0.x*oscale, v0.y*oscale);
          *(__half2*)(C + i1) = __floats2half2_rn(v1.x*oscale, v1.y*oscale);
        }
      }
    }
  }
}

// ---------------------------------------------------------------------------
// Flash attention: 8 warps x 32 q-rows (FM=256), Q frags in registers.
// 4-stage KV ring, one barrier per tile. exp2-domain softmax with
// ex2.approx.f16x2 (P produced directly in half2) and row sums via a
// ones-column MMA (no shuffle reduction). Skip-rescale fast path.
// ---------------------------------------------------------------------------
constexpr int FM = 256, FN = 64, NST = 4;
constexpr int RSW = 36;
constexpr int Q_WORDS = FM*RSW;         // 9216
constexpr int K_WORDS = FN*RSW;         // 2304
constexpr int V_WORDS = FN*RSW;         // 2304
constexpr int NTILES = L_/FN;           // 64
constexpr int FLASH_SMEM = (Q_WORDS + NST*K_WORDS + NST*V_WORDS)*4 + NST*FN*4;

__global__ void __launch_bounds__(256,1) flash_attn(const int* __restrict__ mask)
{
  extern __shared__ uint32_t smw[];
  uint32_t* Qw = smw;                     // [256][36]
  uint32_t* Kw = smw + Q_WORDS;           // [NST][64][36]
  uint32_t* Vw = Kw + NST*K_WORDS;        // [NST][64][36]
  int*      Ms = (int*)(Vw + NST*V_WORDS);

  int tid = threadIdx.x, w = tid>>5, lane = tid&31, g = lane>>2, tg = lane&3;
  int bh = blockIdx.y;
  int b  = bh >> 3;
  int q0 = blockIdx.x * FM;
  int rb = w*32;

  const __half* Qg = g_qh + (size_t)bh*L_*HD_ + (size_t)q0*HD_;
  const __half* Kg = g_kh + (size_t)bh*L_*HD_;
  const __half* Vg = g_vt + (size_t)bh*HD_*L_;
  const int*    mg = mask + b*L_;
  const int*    mf = g_mflag + b*64;

  uint32_t smem_base = (uint32_t)__cvta_generic_to_shared(smw);
  int t8  = lane & 7;
  int lb1 = (lane>>3) & 1;
  int lb2 = lane>>4;
  uint32_t qaddr0 = smem_base + (uint32_t)((rb      + lb1*8 + t8)*RSW + lb2*4)*4;
  uint32_t qaddr1 = smem_base + (uint32_t)((rb + 16 + lb1*8 + t8)*RSW + lb2*4)*4;
  uint32_t kvoff = (uint32_t)(((lb2*8 + t8)*RSW) + lb1*4)*4;
  uint32_t kbase = smem_base + (uint32_t)Q_WORDS*4 + kvoff;
  uint32_t vbase = smem_base + (uint32_t)(Q_WORDS + NST*K_WORDS)*4 + kvoff;
  constexpr uint32_t PSTRIDE = 16*RSW*4;
  constexpr uint32_t KBUF = K_WORDS*4, VBUF = V_WORDS*4;
  const uint32_t ONES2[2] = {0x3C003C00u, 0x3C003C00u};   // half2(1,1) x2

  // Q tile: 256 rows x 8 chunks
  #pragma unroll
  for(int j=0;j<8;j++){
    int idx = tid + j*256;
    int r = idx>>3, c = idx&7;
    cpa16((char*)(Qw + r*RSW) + c*16, Qg + (size_t)r*HD_ + c*8);
  }
  cpa_commit();

  auto loadKV = [&](int st, int it){
    const __half* kg = Kg + (size_t)it*FN*HD_;
    const __half* vg = Vg + it*FN;
    #pragma unroll
    for(int j=0;j<2;j++){
      int idx = tid + j*256;
      int r = idx>>3, c = idx&7;
      cpa16((char*)(Kw + st*K_WORDS + r*RSW) + c*16, kg + (size_t)r*HD_ + c*8);
    }
    #pragma unroll
    for(int j=0;j<2;j++){
      int idx = tid + j*256;
      int r = idx>>3, c = idx&7;
      cpa16((char*)(Vw + st*V_WORDS + r*RSW) + c*16, vg + (size_t)r*L_ + c*8);
    }
    if(tid < 16) cpa16(&Ms[st*FN + tid*4], mg + it*FN + tid*4);
  };

  // Q -> registers (loop invariant)
  cpa_wait<0>();
  __syncthreads();
  uint32_t qf[2][4][4];
  #pragma unroll
  for(int kk=0;kk<4;kk++){
    ldsm4(qf[0][kk][0],qf[0][kk][1],qf[0][kk][2],qf[0][kk][3], qaddr0 + kk*32);
    ldsm4(qf[1][kk][0],qf[1][kk][1],qf[1][kk][2],qf[1][kk][3], qaddr1 + kk*32);
  }

  loadKV(0,0); cpa_commit();
  loadKV(1,1); cpa_commit();

  float o[2][8][4];
  #pragma unroll
  for(int m=0;m<2;m++)
    #pragma unroll
    for(int i=0;i<8;i++)
      #pragma unroll
      for(int j=0;j<4;j++) o[m][i][j]=0.f;
  float mo[4] = {-1e30f,-1e30f,-1e30f,-1e30f};
  float lo[4] = {0.f,0.f,0.f,0.f};

  #pragma unroll 1
  for(int it=0; it<NTILES; it++){
    if(it+2 < NTILES){ loadKV((it+2)&(NST-1), it+2); cpa_commit(); cpa_wait<2>(); }
    else             { cpa_wait<0>(); }
    __syncthreads();                       // single barrier per tile

    int st = it&(NST-1);
    uint32_t kab = kbase + st*KBUF;
    uint32_t vab = vbase + st*VBUF;
    const int* ms = Ms + st*FN;
    int mflag = mf[it];

    float s[2][8][4];
    #pragma unroll
    for(int m=0;m<2;m++)
      #pragma unroll
      for(int i=0;i<8;i++)
        #pragma unroll
        for(int j=0;j<4;j++) s[m][i][j]=0.f;

    #pragma unroll
    for(int kk=0; kk<4; kk++){
      #pragma unroll
      for(int p=0;p<4;p++){
        uint32_t b0,b1,b2,b3;
        ldsm4(b0,b1,b2,b3, kab + p*PSTRIDE + kk*32);
        uint32_t bfa[2] = {b0,b1}, bfb[2] = {b2,b3};
        mma_f16(s[0][2*p  ], qf[0][kk], bfa);
        mma_f16(s[0][2*p+1], qf[0][kk], bfb);
        mma_f16(s[1][2*p  ], qf[1][kk], bfa);
        mma_f16(s[1][2*p+1], qf[1][kk], bfb);
      }
    }

    if(!mflag){
      #pragma unroll
      for(int m=0;m<2;m++)
        #pragma unroll
        for(int in=0;in<8;in++){
          int c0 = in*8 + tg*2;
          bool ok0 = ms[c0]!=0, ok1 = ms[c0+1]!=0;
          s[m][in][0] = ok0 ? s[m][in][0] : -1e30f;
          s[m][in][1] = ok1 ? s[m][in][1] : -1e30f;
          s[m][in][2] = ok0 ? s[m][in][2] : -1e30f;
          s[m][in][3] = ok1 ? s[m][in][3] : -1e30f;
        }
    }

    // softmax: max-reduce (fp32), pack (s-mn) -> half2, exp via ex2.f16x2.
    // P lives in ph[m][16] half2 regs, ordered for the PV A-fragments.
    uint32_t ph[2][16];
    #pragma unroll
    for(int m=0;m<2;m++){
      float mx0=-1e30f, mx1=-1e30f;
      #pragma unroll
      for(int in=0;in<8;in++){
        mx0 = fmaxf(mx0, fmaxf(s[m][in][0], s[m][in][1]));
        mx1 = fmaxf(mx1, fmaxf(s[m][in][2], s[m][in][3]));
      }
      mx0 = fmaxf(mx0, __shfl_xor_sync(0xffffffffu, mx0, 1));
      mx0 = fmaxf(mx0, __shfl_xor_sync(0xffffffffu, mx0, 2));
      mx1 = fmaxf(mx1, __shfl_xor_sync(0xffffffffu, mx1, 1));
      mx1 = fmaxf(mx1, __shfl_xor_sync(0xffffffffu, mx1, 2));

      float mn0, mn1;
      bool up = (mx0 > mo[2*m]) || (mx1 > mo[2*m+1]);
      if(__any_sync(0xffffffffu, up)){
        mn0 = fmaxf(mo[2*m], mx0); mn1 = fmaxf(mo[2*m+1], mx1);
        float sc0 = exp2f(mo[2*m] - mn0), sc1 = exp2f(mo[2*m+1] - mn1);
        lo[2*m] *= sc0; lo[2*m+1] *= sc1;
        mo[2*m] = mn0;  mo[2*m+1] = mn1;
        #pragma unroll
        for(int in=0;in<8;in++){
          o[m][in][0]*=sc0; o[m][in][1]*=sc0; o[m][in][2]*=sc1; o[m][in][3]*=sc1;
        }
      } else {
        mn0 = mo[2*m]; mn1 = mo[2*m+1];
      }

      #pragma unroll
      for(int in=0;in<8;in++){
        ph[m][2*in  ] = ex2h2(h2u(__floats2half2_rn(s[m][in][0]-mn0, s[m][in][1]-mn0)));
        ph[m][2*in+1] = ex2h2(h2u(__floats2half2_rn(s[m][in][2]-mn1, s[m][in][3]-mn1)));
      }
    }

    // row sums via ones-column MMA: every lane's c[0]/c[2] = full row sum
    float sum0[4] = {0.f,0.f,0.f,0.f};
    float sum1[4] = {0.f,0.f,0.f,0.f};
    #pragma unroll
    for(int kb=0;kb<4;kb++){
      mma_f16(sum0, &ph[0][4*kb], ONES2);
      mma_f16(sum1, &ph[1][4*kb], ONES2);
    }
    lo[0] += sum0[0]; lo[1] += sum0[2];
    lo[2] += sum1[0]; lo[3] += sum1[2];

    // O += P @ V
    #pragma unroll
    for(int kb=0;kb<4;kb++){
      #pragma unroll
      for(int p=0;p<4;p++){
        uint32_t b0,b1,b2,b3;
        ldsm4(b0,b1,b2,b3, vab + p*PSTRIDE + kb*32);
        uint32_t bfa[2] = {b0,b1}, bfb[2] = {b2,b3};
        mma_f16(o[0][2*p  ], &ph[0][4*kb], bfa);
        mma_f16(o[0][2*p+1], &ph[0][4*kb], bfb);
        mma_f16(o[1][2*p  ], &ph[1][4*kb], bfa);
        mma_f16(o[1][2*p+1], &ph[1][4*kb], bfb);
      }
    }
    // no trailing barrier: 4-stage ring tolerates a full tile of warp skew
  }

  #pragma unroll
  for(int m=0;m<2;m++){
    float inv0 = 1.f/lo[2*m], inv1 = 1.f/lo[2*m+1];
    int r0 = q0 + rb + m*16 + g;
    __half* op0 = g_ctx16 + (size_t)(b*L_ + r0    )*D_ + (bh&7)*HD_;
    __half* op1 = g_ctx16 + (size_t)(b*L_ + r0 + 8)*D_ + (bh&7)*HD_;
    #pragma unroll
    for(int in=0;in<8;in++){
      int d = in*8 + tg*2;
      *(__half2*)(op0 + d) = __floats2half2_rn(o[m][in][0]*inv0, o[m][in][1]*inv0);
      *(__half2*)(op1 + d) = __floats2half2_rn(o[m][in][2]*inv1, o[m][in][3]*inv1);
    }
  }
}

// ---------------------------------------------------------------------------
extern "C" void kernel_launch(void* const* d_in, const int* in_sizes, int n_in,
                              void* d_out, int out_size)
{
  (void)in_sizes; (void)n_in; (void)out_size;
  const float* query = (const float*)d_in[0];
  const float* key   = (const float*)d_in[1];
  const float* value = (const float*)d_in[2];
  const int*   mask  = (const int*)d_in[3];
  const float* Wq = (const float*)d_in[4];
  const float* bq = (const float*)d_in[5];
  const float* Wk = (const float*)d_in[6];
  const float* bk = (const float*)d_in[7];
  const float* Wv = (const float*)d_in[8];
  const float* bv = (const float*)d_in[9];
  const float* Wo = (const float*)d_in[10];
  const float* bo = (const float*)d_in[11];
  float* out = (float*)d_out;

  static bool attr_done = false;
  if(!attr_done){
    cudaFuncSetAttribute(gemm_f16,   cudaFuncAttributeMaxDynamicSharedMemorySize, GEMM16_SMEM);
    cudaFuncSetAttribute(flash_attn, cudaFuncAttributeMaxDynamicSharedMemorySize, FLASH_SMEM);
    attr_done = true;
  }

  conv16<<<(int)(MD/4/256), 256>>>(query, key, value, Wq, Wk, Wv, Wo, mask);

  dim3 gq(D_/GBN, M_/GBM, 3);       // (4, 64, 3) — QKV fused
  gemm_f16<<<gq, 256, GEMM16_SMEM>>>(bq, bk, bv, bo, nullptr, 1);

  dim3 fg(L_/FM, B_*H_);            // (16, 16)
  flash_attn<<<fg, 256, FLASH_SMEM>>>(mask);

  dim3 go(D_/GBN, M_/GBM, 1);       // (4, 64) — output projection
  gemm_f16<<<go, 256, GEMM16_SMEM>>>(bq, bk, bv, bo, out, 4);
}

// round 12
// speedup vs baseline: 1.1088x; 1.0669x over previous
#include <cuda_runtime.h>
#include <cuda_fp16.h>
#include <cstdint>

#define DEVI __device__ __forceinline__

constexpr int B_  = 2;
constexpr int L_  = 4096;
constexpr int D_  = 512;
constexpr int H_  = 8;
constexpr int HD_ = 64;
constexpr int M_  = B_ * L_;          // 8192
constexpr size_t MD = (size_t)M_*D_;  // 4194304
constexpr size_t DD = (size_t)D_*D_;  // 262144

// scratch: __device__ globals (allocation-free rule)
__device__ __half g_x16[3*MD];          // fp16 copies of query,key,value
__device__ __half g_w16[4*DD];          // fp16 copies of Wq,Wk,Wv,Wo
__device__ __half g_qh[B_*H_*L_*HD_];   // [b,h,l,d] (pre-scaled by 0.125*log2e)
__device__ __half g_kh[B_*H_*L_*HD_];   // [b,h,l,d]
__device__ __half g_vt[B_*H_*HD_*L_];   // [b,h,d,l]  (transposed)
__device__ __half g_ctx16[MD];          // attention output, fp16
__device__ int    g_mflag[B_*64];       // 1 if 64-key block fully valid

DEVI uint32_t h2u(__half2 h){ union{ __half2 h; uint32_t u; } c; c.h = h; return c.u; }

DEVI void mma_f16(float* c, const uint32_t* a, const uint32_t* b){
  asm volatile("mma.sync.aligned.m16n8k16.row.col.f32.f16.f16.f32 "
    "{%0,%1,%2,%3},{%4,%5,%6,%7},{%8,%9},{%0,%1,%2,%3};\n"
    : "+f"(c[0]),"+f"(c[1]),"+f"(c[2]),"+f"(c[3])
    : "r"(a[0]),"r"(a[1]),"r"(a[2]),"r"(a[3]),"r"(b[0]),"r"(b[1]));
}

DEVI uint32_t ex2h2(uint32_t x){
  uint32_t r;
  asm("ex2.approx.f16x2 %0, %1;" : "=r"(r) : "r"(x));
  return r;
}

DEVI void ldsm4(uint32_t& r0, uint32_t& r1, uint32_t& r2, uint32_t& r3, uint32_t addr){
  asm volatile("ldmatrix.sync.aligned.m8n8.x4.shared.b16 {%0,%1,%2,%3}, [%4];"
    : "=r"(r0),"=r"(r1),"=r"(r2),"=r"(r3) : "r"(addr));
}
DEVI void ldsm4t(uint32_t& r0, uint32_t& r1, uint32_t& r2, uint32_t& r3, uint32_t addr){
  asm volatile("ldmatrix.sync.aligned.m8n8.x4.trans.shared.b16 {%0,%1,%2,%3}, [%4];"
    : "=r"(r0),"=r"(r1),"=r"(r2),"=r"(r3) : "r"(addr));
}

DEVI void cpa16(void* s, const void* g){
  uint32_t sa = (uint32_t)__cvta_generic_to_shared(s);
  asm volatile("cp.async.cg.shared.global [%0], [%1], 16;\n"::"r"(sa),"l"(g));
}
DEVI void cpa_commit(){ asm volatile("cp.async.commit_group;\n"); }
template<int N> DEVI void cpa_wait(){ asm volatile("cp.async.wait_group %0;\n"::"n"(N)); }

// ---- mbarrier helpers (flash pipeline) ----
DEVI void mbar_init(uint32_t a, uint32_t cnt){
  asm volatile("mbarrier.init.shared.b64 [%0], %1;"::"r"(a),"r"(cnt):"memory");
}
DEVI void mbar_arrive(uint32_t a){
  asm volatile("mbarrier.arrive.shared.b64 _, [%0];"::"r"(a):"memory");
}
DEVI void cp_arrive(uint32_t a){
  asm volatile("cp.async.mbarrier.arrive.noinc.shared.b64 [%0];"::"r"(a):"memory");
}
DEVI void mbar_wait(uint32_t a, uint32_t ph){
  uint32_t done;
  asm volatile(
    "{\n\t.reg .pred p;\n\t"
    "mbarrier.try_wait.parity.acquire.cta.shared::cta.b64 p, [%1], %2;\n\t"
    "selp.b32 %0, 1, 0, p;\n\t}"
    : "=r"(done) : "r"(a), "r"(ph) : "memory");
  if(!done){
    asm volatile(
      "{\n\t.reg .pred P1;\n\t"
      "W_%=:\n\t"
      "mbarrier.try_wait.parity.acquire.cta.shared::cta.b64 P1, [%0], %1, 0x989680;\n\t"
      "@P1 bra.uni D_%=;\n\t"
      "bra.uni W_%=;\n\t"
      "D_%=:\n\t}"
      :: "r"(a), "r"(ph) : "memory");
  }
}

// ---------------------------------------------------------------------------
// conv16: round inputs + weights to fp16 once; also mask block flags
// ---------------------------------------------------------------------------
__global__ void conv16(const float* __restrict__ q, const float* __restrict__ k,
                       const float* __restrict__ v,
                       const float* __restrict__ wq, const float* __restrict__ wk,
                       const float* __restrict__ wv, const float* __restrict__ wo,
                       const int* __restrict__ mask)
{
  size_t i = ((size_t)blockIdx.x*blockDim.x + threadIdx.x)*4;
  if(i < MD){
    float4 a;
    a = *(const float4*)(q+i);
    *(__half2*)(g_x16 + i)        = __floats2half2_rn(a.x,a.y);
    *(__half2*)(g_x16 + i + 2)    = __floats2half2_rn(a.z,a.w);
    a = *(const float4*)(k+i);
    *(__half2*)(g_x16 + MD + i)   = __floats2half2_rn(a.x,a.y);
    *(__half2*)(g_x16 + MD + i+2) = __floats2half2_rn(a.z,a.w);
    a = *(const float4*)(v+i);
    *(__half2*)(g_x16 + 2*MD + i)   = __floats2half2_rn(a.x,a.y);
    *(__half2*)(g_x16 + 2*MD + i+2) = __floats2half2_rn(a.z,a.w);
  }
  if(i < DD){
    float4 a;
    a = *(const float4*)(wq+i);
    *(__half2*)(g_w16 + i)        = __floats2half2_rn(a.x,a.y);
    *(__half2*)(g_w16 + i + 2)    = __floats2half2_rn(a.z,a.w);
    a = *(const float4*)(wk+i);
    *(__half2*)(g_w16 + DD + i)   = __floats2half2_rn(a.x,a.y);
    *(__half2*)(g_w16 + DD + i+2) = __floats2half2_rn(a.z,a.w);
    a = *(const float4*)(wv+i);
    *(__half2*)(g_w16 + 2*DD + i)   = __floats2half2_rn(a.x,a.y);
    *(__half2*)(g_w16 + 2*DD + i+2) = __floats2half2_rn(a.z,a.w);
    a = *(const float4*)(wo+i);
    *(__half2*)(g_w16 + 3*DD + i)   = __floats2half2_rn(a.x,a.y);
    *(__half2*)(g_w16 + 3*DD + i+2) = __floats2half2_rn(a.z,a.w);
  }
  if(blockIdx.x == 0 && threadIdx.x < B_*64){
    int b = threadIdx.x >> 6, t = threadIdx.x & 63;
    const int* mp = mask + b*L_ + t*64;
    int ok = 1;
    #pragma unroll 8
    for(int j=0;j<64;j++) ok &= (mp[j]!=0);
    g_mflag[threadIdx.x] = ok;
  }
}

// ---------------------------------------------------------------------------
// fp16 GEMM: C[M,512] = A[M,512] @ W[512,512] + bias   (fp32 accum)
// ---------------------------------------------------------------------------
constexpr int GBM = 128, GBN = 128, GBK = 64;
constexpr int GAW = 36;
constexpr int GBW = 68;
constexpr int GA_WORDS = GBM*GAW;   // 4608
constexpr int GB_WORDS = GBK*GBW;   // 4352
constexpr int GEMM16_SMEM = (2*GA_WORDS + 2*GB_WORDS)*4;   // 71680

__global__ void __launch_bounds__(256,2) gemm_f16(
  const float* __restrict__ bq, const float* __restrict__ bk,
  const float* __restrict__ bv, const float* __restrict__ bo,
  float* __restrict__ out, int mode_base)
{
  extern __shared__ uint32_t smw[];
  uint32_t* Aw = smw;
  uint32_t* Bw = smw + 2*GA_WORDS;

  int mode = mode_base + blockIdx.z;     // 1..3 or 4
  const __half* A = (mode==4) ? g_ctx16 : g_x16 + (size_t)(mode-1)*MD;
  const __half* W = g_w16 + (size_t)(mode-1)*DD;
  const float* bias = (mode==1)?bq : (mode==2)?bk : (mode==3)?bv : bo;

  int tid = threadIdx.x;
  int m0 = blockIdx.y*GBM, n0 = blockIdx.x*GBN;
  int w = tid>>5, lane = tid&31, g = lane>>2, tg = lane&3;
  int wm = (w>>1)*32, wn = (w&1)*64;

  uint32_t sbase = (uint32_t)__cvta_generic_to_shared(smw);
  int t8  = lane & 7;
  int lb1 = (lane>>3) & 1;
  int lb2 = lane>>4;
  uint32_t a0 = sbase + (uint32_t)((wm      + lb1*8 + t8)*GAW + lb2*4)*4;
  uint32_t a1 = sbase + (uint32_t)((wm + 16 + lb1*8 + t8)*GAW + lb2*4)*4;
  uint32_t bb = sbase + (uint32_t)(2*GA_WORDS)*4
              + (uint32_t)((lb1*8 + t8)*GBW)*4 + (uint32_t)(wn + lb2*8)*2;
  constexpr uint32_t ABUF = GA_WORDS*4, BBUF = GB_WORDS*4;
  constexpr uint32_t BKSTEP = 16*GBW*4;

  float acc[2][8][4];
  #pragma unroll
  for(int i=0;i<2;i++)
    #pragma unroll
    for(int j=0;j<8;j++)
      #pragma unroll
      for(int k2=0;k2<4;k2++) acc[i][j][k2]=0.f;

  auto load_tiles = [&](int buf, int kt){
    const __half* ga = A + (size_t)m0*D_ + kt*GBK;
    #pragma unroll
    for(int j=0;j<4;j++){
      int idx = tid + j*256;
      int r = idx>>3, c = idx&7;
      cpa16((char*)(Aw + buf*GA_WORDS + r*GAW) + c*16, ga + (size_t)r*D_ + c*8);
    }
    const __half* gb = W + (size_t)(kt*GBK)*D_ + n0;
    #pragma unroll
    for(int j=0;j<4;j++){
      int idx = tid + j*256;
      int r = idx>>4, c = idx&15;
      cpa16((char*)(Bw + buf*GB_WORDS + r*GBW) + c*16, gb + (size_t)r*D_ + c*8);
    }
  };

  load_tiles(0,0); cpa_commit();

  #pragma unroll 1
  for(int kt=0; kt<D_/GBK; kt++){
    if(kt+1 < D_/GBK){ load_tiles((kt+1)&1, kt+1); cpa_commit(); cpa_wait<1>(); }
    else             { cpa_wait<0>(); }
    __syncthreads();
    int buf = kt&1;
    uint32_t ac0 = a0 + buf*ABUF, ac1 = a1 + buf*ABUF;
    uint32_t bc  = bb + buf*BBUF;
    #pragma unroll
    for(int kk=0; kk<4; kk++){
      uint32_t af0[4], af1[4];
      ldsm4(af0[0],af0[1],af0[2],af0[3], ac0 + kk*32);
      ldsm4(af1[0],af1[1],af1[2],af1[3], ac1 + kk*32);
      #pragma unroll
      for(int j=0;j<4;j++){
        uint32_t b0,b1,b2,b3;
        ldsm4t(b0,b1,b2,b3, bc + kk*BKSTEP + j*32);
        uint32_t bfa[2] = {b0,b1}, bfb[2] = {b2,b3};
        mma_f16(acc[0][2*j  ], af0, bfa);
        mma_f16(acc[0][2*j+1], af0, bfb);
        mma_f16(acc[1][2*j  ], af1, bfa);
        mma_f16(acc[1][2*j+1], af1, bfb);
      }
    }
    __syncthreads();
  }

  float oscale = (mode==1) ? 0.125f*1.44269504f : 1.0f;
  #pragma unroll
  for(int im=0;im<2;im++){
    int r0 = m0 + wm + im*16 + g;
    int r8 = r0 + 8;
    #pragma unroll
    for(int in=0;in<8;in++){
      int col = n0 + wn + in*8 + tg*2;
      float bx = bias[col], by = bias[col+1];
      float2 v0 = make_float2(acc[im][in][0]+bx, acc[im][in][1]+by);
      float2 v1 = make_float2(acc[im][in][2]+bx, acc[im][in][3]+by);
      if(mode==4){
        *(float2*)(out + (size_t)r0*D_ + col) = v0;
        *(float2*)(out + (size_t)r8*D_ + col) = v1;
      } else {
        int h = col>>6, d = col&63;
        int b0i = r0>>12, t0 = r0&4095;
        int b1i = r8>>12, t1 = r8&4095;
        if(mode==3){
          size_t i0 = ((size_t)(b0i*H_ + h)*HD_ + d)*L_ + t0;
          size_t i1 = ((size_t)(b1i*H_ + h)*HD_ + d)*L_ + t1;
          g_vt[i0]      = __float2half_rn(v0.x);
          g_vt[i0 + L_] = __float2half_rn(v0.y);
          g_vt[i1]      = __float2half_rn(v1.x);
          g_vt[i1 + L_] = __float2half_rn(v1.y);
        } else {
          __half* C = (mode==1) ? g_qh : g_kh;
          size_t i0 = ((size_t)(b0i*H_ + h)*L_ + t0)*HD_ + d;
          size_t i1 = ((size_t)(b1i*H_ + h)*L_ + t1)*HD_ + d;
          *(__half2*)(C + i0) = __floats2half2_rn(v0.x*oscale, v0.y*oscale);
          *(__half2*)(C + i1) = __floats2half2_rn(v1.x*oscale, v1.y*oscale);
        }
      }
    }
  }
}

// ---------------------------------------------------------------------------
// Flash attention: 8 warps x 32 q-rows (FM=256), Q frags in registers.
// BARRIER-FREE mainloop: 4-stage KV ring synced via mbarriers.
// cp.async completion -> full[st] (cp.async.mbarrier.arrive.noinc, 256 arrivals)
// consumers arrive empty[st] after use; issuers wait empty before refill.
// Warps skew up to ~2 tiles: softmax of one warp overlaps MMAs of another.
// ---------------------------------------------------------------------------
constexpr int FM = 256, FN = 64, NST = 4;
constexpr int RSW = 36;
constexpr int Q_WORDS = FM*RSW;         // 9216
constexpr int K_WORDS = FN*RSW;         // 2304
constexpr int V_WORDS = FN*RSW;         // 2304
constexpr int NTILES = L_/FN;           // 64
constexpr int PIPE_WORDS = Q_WORDS + NST*(K_WORDS+V_WORDS);  // 27648
constexpr int FLASH_SMEM = PIPE_WORDS*4 + 64;                // + 8 mbarriers

__global__ void __launch_bounds__(256,1) flash_attn(const int* __restrict__ mask)
{
  extern __shared__ uint32_t smw[];
  uint32_t* Qw = smw;                     // [256][36]
  uint32_t* Kw = smw + Q_WORDS;           // [NST][64][36]
  uint32_t* Vw = Kw + NST*K_WORDS;        // [NST][64][36]

  int tid = threadIdx.x, w = tid>>5, lane = tid&31, g = lane>>2, tg = lane&3;
  int bh = blockIdx.y;
  int b  = bh >> 3;
  int q0 = blockIdx.x * FM;
  int rb = w*32;

  const __half* Qg = g_qh + (size_t)bh*L_*HD_ + (size_t)q0*HD_;
  const __half* Kg = g_kh + (size_t)bh*L_*HD_;
  const __half* Vg = g_vt + (size_t)bh*HD_*L_;
  const int*    mg = mask + b*L_;
  const int*    mf = g_mflag + b*64;

  uint32_t smem_base = (uint32_t)__cvta_generic_to_shared(smw);
  uint32_t mb = smem_base + (uint32_t)PIPE_WORDS*4;   // 8 mbarriers (8B each)
  auto FULLB  = [&](int s){ return mb + (uint32_t)s*8; };
  auto EMPTYB = [&](int s){ return mb + 32u + (uint32_t)s*8; };

  int t8  = lane & 7;
  int lb1 = (lane>>3) & 1;
  int lb2 = lane>>4;
  uint32_t qaddr0 = smem_base + (uint32_t)((rb      + lb1*8 + t8)*RSW + lb2*4)*4;
  uint32_t qaddr1 = smem_base + (uint32_t)((rb + 16 + lb1*8 + t8)*RSW + lb2*4)*4;
  uint32_t kvoff = (uint32_t)(((lb2*8 + t8)*RSW) + lb1*4)*4;
  uint32_t kbase = smem_base + (uint32_t)Q_WORDS*4 + kvoff;
  uint32_t vbase = smem_base + (uint32_t)(Q_WORDS + NST*K_WORDS)*4 + kvoff;
  constexpr uint32_t PSTRIDE = 16*RSW*4;
  constexpr uint32_t KBUF = K_WORDS*4, VBUF = V_WORDS*4;
  const uint32_t ONES2[2] = {0x3C003C00u, 0x3C003C00u};   // half2(1,1) x2

  // init mbarriers (every launch; graph replay re-inits)
  if(tid == 0){
    #pragma unroll
    for(int s=0;s<NST;s++){
      mbar_init(FULLB(s), 256);
      mbar_init(EMPTYB(s), 256);
    }
  }
  __syncthreads();

  auto loadKV = [&](int st, int it){
    const __half* kg = Kg + (size_t)it*FN*HD_;
    const __half* vg = Vg + it*FN;
    #pragma unroll
    for(int j=0;j<2;j++){
      int idx = tid + j*256;
      int r = idx>>3, c = idx&7;
      cpa16((char*)(Kw + st*K_WORDS + r*RSW) + c*16, kg + (size_t)r*HD_ + c*8);
    }
    #pragma unroll
    for(int j=0;j<2;j++){
      int idx = tid + j*256;
      int r = idx>>3, c = idx&7;
      cpa16((char*)(Vw + st*V_WORDS + r*RSW) + c*16, vg + (size_t)r*L_ + c*8);
    }
  };

  // Q tile + first two KV tiles
  #pragma unroll
  for(int j=0;j<8;j++){
    int idx = tid + j*256;
    int r = idx>>3, c = idx&7;
    cpa16((char*)(Qw + r*RSW) + c*16, Qg + (size_t)r*HD_ + c*8);
  }
  loadKV(0,0); cp_arrive(FULLB(0));   // tracks Q + tile0 cp.asyncs
  loadKV(1,1); cp_arrive(FULLB(1));

  // Q -> registers (FULL[0] completion => Q visible CTA-wide)
  mbar_wait(FULLB(0), 0);
  uint32_t qf[2][4][4];
  #pragma unroll
  for(int kk=0;kk<4;kk++){
    ldsm4(qf[0][kk][0],qf[0][kk][1],qf[0][kk][2],qf[0][kk][3], qaddr0 + kk*32);
    ldsm4(qf[1][kk][0],qf[1][kk][1],qf[1][kk][2],qf[1][kk][3], qaddr1 + kk*32);
  }

  float o[2][8][4];
  #pragma unroll
  for(int m=0;m<2;m++)
    #pragma unroll
    for(int i=0;i<8;i++)
      #pragma unroll
      for(int j=0;j<4;j++) o[m][i][j]=0.f;
  float mo[4] = {-1e30f,-1e30f,-1e30f,-1e30f};
  float lo[4] = {0.f,0.f,0.f,0.f};

  #pragma unroll 1
  for(int it=0; it<NTILES; it++){
    // refill stage for tile it+2 (each thread issues its own share)
    int tp = it+2;
    if(tp < NTILES){
      int stp = tp & (NST-1);
      if(tp >= NST) mbar_wait(EMPTYB(stp), ((tp>>2)+1)&1);
      loadKV(stp, tp);
      cp_arrive(FULLB(stp));
    }

    int st = it & (NST-1);
    int ph = (it>>2) & 1;
    mbar_wait(FULLB(st), ph);

    uint32_t kab = kbase + st*KBUF;
    uint32_t vab = vbase + st*VBUF;
    int mflag = mf[it];

    float s[2][8][4];
    #pragma unroll
    for(int m=0;m<2;m++)
      #pragma unroll
      for(int i=0;i<8;i++)
        #pragma unroll
        for(int j=0;j<4;j++) s[m][i][j]=0.f;

    #pragma unroll
    for(int kk=0; kk<4; kk++){
      #pragma unroll
      for(int p=0;p<4;p++){
        uint32_t b0,b1,b2,b3;
        ldsm4(b0,b1,b2,b3, kab + p*PSTRIDE + kk*32);
        uint32_t bfa[2] = {b0,b1}, bfb[2] = {b2,b3};
        mma_f16(s[0][2*p  ], qf[0][kk], bfa);
        mma_f16(s[0][2*p+1], qf[0][kk], bfb);
        mma_f16(s[1][2*p  ], qf[1][kk], bfa);
        mma_f16(s[1][2*p+1], qf[1][kk], bfb);
      }
    }

    if(!mflag){                      // rare path: direct LDG of mask ints
      const int* mrow = mg + it*FN;
      #pragma unroll
      for(int m=0;m<2;m++)
        #pragma unroll
        for(int in=0;in<8;in++){
          int c0 = in*8 + tg*2;
          bool ok0 = mrow[c0]!=0, ok1 = mrow[c0+1]!=0;
          s[m][in][0] = ok0 ? s[m][in][0] : -1e30f;
          s[m][in][1] = ok1 ? s[m][in][1] : -1e30f;
          s[m][in][2] = ok0 ? s[m][in][2] : -1e30f;
          s[m][in][3] = ok1 ? s[m][in][3] : -1e30f;
        }
    }

    // softmax: fp32 max-reduce, pack (s-mn) -> half2, ex2.f16x2
    uint32_t phh[2][16];
    #pragma unroll
    for(int m=0;m<2;m++){
      float mx0=-1e30f, mx1=-1e30f;
      #pragma unroll
      for(int in=0;in<8;in++){
        mx0 = fmaxf(mx0, fmaxf(s[m][in][0], s[m][in][1]));
        mx1 = fmaxf(mx1, fmaxf(s[m][in][2], s[m][in][3]));
      }
      mx0 = fmaxf(mx0, __shfl_xor_sync(0xffffffffu, mx0, 1));
      mx0 = fmaxf(mx0, __shfl_xor_sync(0xffffffffu, mx0, 2));
      mx1 = fmaxf(mx1, __shfl_xor_sync(0xffffffffu, mx1, 1));
      mx1 = fmaxf(mx1, __shfl_xor_sync(0xffffffffu, mx1, 2));

      float mn0, mn1;
      bool up = (mx0 > mo[2*m]) || (mx1 > mo[2*m+1]);
      if(__any_sync(0xffffffffu, up)){
        mn0 = fmaxf(mo[2*m], mx0); mn1 = fmaxf(mo[2*m+1], mx1);
        float sc0 = exp2f(mo[2*m] - mn0), sc1 = exp2f(mo[2*m+1] - mn1);
        lo[2*m] *= sc0; lo[2*m+1] *= sc1;
        mo[2*m] = mn0;  mo[2*m+1] = mn1;
        #pragma unroll
        for(int in=0;in<8;in++){
          o[m][in][0]*=sc0; o[m][in][1]*=sc0; o[m][in][2]*=sc1; o[m][in][3]*=sc1;
        }
      } else {
        mn0 = mo[2*m]; mn1 = mo[2*m+1];
      }

      #pragma unroll
      for(int in=0;in<8;in++){
        phh[m][2*in  ] = ex2h2(h2u(__floats2half2_rn(s[m][in][0]-mn0, s[m][in][1]-mn0)));
        phh[m][2*in+1] = ex2h2(h2u(__floats2half2_rn(s[m][in][2]-mn1, s[m][in][3]-mn1)));
      }
    }

    // row sums via ones-column MMA
    float sum0[4] = {0.f,0.f,0.f,0.f};
    float sum1[4] = {0.f,0.f,0.f,0.f};
    #pragma unroll
    for(int kb=0;kb<4;kb++){
      mma_f16(sum0, &phh[0][4*kb], ONES2);
      mma_f16(sum1, &phh[1][4*kb], ONES2);
    }
    lo[0] += sum0[0]; lo[1] += sum0[2];
    lo[2] += sum1[0]; lo[3] += sum1[2];

    // O += P @ V
    #pragma unroll
    for(int kb=0;kb<4;kb++){
      #pragma unroll
      for(int p=0;p<4;p++){
        uint32_t b0,b1,b2,b3;
        ldsm4(b0,b1,b2,b3, vab + p*PSTRIDE + kb*32);
        uint32_t bfa[2] = {b0,b1}, bfb[2] = {b2,b3};
        mma_f16(o[0][2*p  ], &phh[0][4*kb], bfa);
        mma_f16(o[0][2*p+1], &phh[0][4*kb], bfb);
        mma_f16(o[1][2*p  ], &phh[1][4*kb], bfa);
        mma_f16(o[1][2*p+1], &phh[1][4*kb], bfb);
      }
    }

    mbar_arrive(EMPTYB(st));   // done reading stage st
  }

  #pragma unroll
  for(int m=0;m<2;m++){
    float inv0 = 1.f/lo[2*m], inv1 = 1.f/lo[2*m+1];
    int r0 = q0 + rb + m*16 + g;
    __half* op0 = g_ctx16 + (size_t)(b*L_ + r0    )*D_ + (bh&7)*HD_;
    __half* op1 = g_ctx16 + (size_t)(b*L_ + r0 + 8)*D_ + (bh&7)*HD_;
    #pragma unroll
    for(int in=0;in<8;in++){
      int d = in*8 + tg*2;
      *(__half2*)(op0 + d) = __floats2half2_rn(o[m][in][0]*inv0, o[m][in][1]*inv0);
      *(__half2*)(op1 + d) = __floats2half2_rn(o[m][in][2]*inv1, o[m][in][3]*inv1);
    }
  }
}

// ---------------------------------------------------------------------------
extern "C" void kernel_launch(void* const* d_in, const int* in_sizes, int n_in,
                              void* d_out, int out_size)
{
  (void)in_sizes; (void)n_in; (void)out_size;
  const float* query = (const float*)d_in[0];
  const float* key   = (const float*)d_in[1];
  const float* value = (const float*)d_in[2];
  const int*   mask  = (const int*)d_in[3];
  const float* Wq = (const float*)d_in[4];
  const float* bq = (const float*)d_in[5];
  const float* Wk = (const float*)d_in[6];
  const float* bk = (const float*)d_in[7];
  const float* Wv = (const float*)d_in[8];
  const float* bv = (const float*)d_in[9];
  const float* Wo = (const float*)d_in[10];
  const float* bo = (const float*)d_in[11];
  float* out = (float*)d_out;

  static bool attr_done = false;
  if(!attr_done){
    cudaFuncSetAttribute(gemm_f16,   cudaFuncAttributeMaxDynamicSharedMemorySize, GEMM16_SMEM);
    cudaFuncSetAttribute(flash_attn, cudaFuncAttributeMaxDynamicSharedMemorySize, FLASH_SMEM);
    attr_done = true;
  }

  conv16<<<(int)(MD/4/256), 256>>>(query, key, value, Wq, Wk, Wv, Wo, mask);

  dim3 gq(D_/GBN, M_/GBM, 3);       // (4, 64, 3) — QKV fused
  gemm_f16<<<gq, 256, GEMM16_SMEM>>>(bq, bk, bv, bo, nullptr, 1);

  dim3 fg(L_/FM, B_*H_);            // (16, 16)
  flash_attn<<<fg, 256, FLASH_SMEM>>>(mask);

  dim3 go(D_/GBN, M_/GBM, 1);       // (4, 64) — output projection
  gemm_f16<<<go, 256, GEMM16_SMEM>>>(bq, bk, bv, bo, out, 4);
}